// round 13
// baseline (speedup 1.0000x reference)
#include <cuda_runtime.h>
#include <cuda_bf16.h>
#include <cstdint>

// Problem constants (fixed by the dataset)
#define N_NODES 50000
#define N_EDGES 800000
#define DIM     128
#define OUTD    12
#define CAP     128          // per-node in-edge bucket capacity (Poisson(16) degree)

// ---------------------------------------------------------------------------
// Device scratch (no allocations allowed)
// ---------------------------------------------------------------------------
__device__ float g_H[N_NODES * DIM];        // layer buffers (dinv-scaled H')
__device__ float g_B[N_NODES * DIM];
__device__ float g_A[N_NODES * DIM];        // final activations for regress
__device__ float g_Wt[3 * DIM * DIM];       // transposed + tf32-rounded weights
__device__ float g_dinv[N_NODES];
__device__ int   g_cnt[N_NODES];
__device__ int   g_bucket[N_NODES * CAP];   // in-edge src lists per dst

__device__ __forceinline__ uint32_t f2tf32(float f) {
    uint32_t u;
    asm("cvt.rna.tf32.f32 %0, %1;" : "=r"(u) : "f"(f));
    return u;
}

__device__ __forceinline__ uint32_t smem_u32(const void* p) {
    uint32_t a;
    asm("{ .reg .u64 t; cvta.to.shared.u64 t, %1; cvt.u32.u64 %0, t; }" : "=r"(a) : "l"(p));
    return a;
}

__device__ __forceinline__ void mma_tf32(float* d, const uint32_t* a,
                                         uint32_t b0, uint32_t b1) {
    asm volatile(
        "mma.sync.aligned.m16n8k8.row.col.f32.tf32.tf32.f32 "
        "{%0,%1,%2,%3}, {%4,%5,%6,%7}, {%8,%9}, {%0,%1,%2,%3};"
        : "+f"(d[0]), "+f"(d[1]), "+f"(d[2]), "+f"(d[3])
        : "r"(a[0]), "r"(a[1]), "r"(a[2]), "r"(a[3]), "r"(b0), "r"(b1));
}

// ---------------------------------------------------------------------------
// Fused precompute: blocks 0..47 transpose+round weights, rest zero cnt.
// ---------------------------------------------------------------------------
__global__ void k_pre(const float* __restrict__ W1, const float* __restrict__ W2,
                      const float* __restrict__ W3, float* __restrict__ Wt,
                      int* __restrict__ cnt, int n) {
    int b = blockIdx.x;
    int t = threadIdx.x;
    if (b < 48) {
        __shared__ float tile[32][33];
        int bz = b >> 4, rem = b & 15, bx = rem & 3, by = rem >> 2;
        const float* W = (bz == 0) ? W1 : (bz == 1) ? W2 : W3;
        float* dst = Wt + (size_t)bz * DIM * DIM;
        int tx = t & 31, ty = t >> 5;
        int x = bx * 32 + tx, y = by * 32 + ty;
#pragma unroll
        for (int j = 0; j < 32; j += 8)
            tile[ty + j][tx] = W[(y + j) * DIM + x];
        __syncthreads();
        x = by * 32 + tx; y = bx * 32 + ty;
#pragma unroll
        for (int j = 0; j < 32; j += 8)
            dst[(y + j) * DIM + x] = __uint_as_float(f2tf32(tile[tx][ty + j]));
    } else {
        int i = (b - 48) * 256 + t;
        if (i < n) cnt[i] = 0;
    }
}

__global__ void k_fill(const int* __restrict__ src, const int* __restrict__ dst,
                       int* cnt, int* bucket, int E) {
    int e = blockIdx.x * blockDim.x + threadIdx.x;
    if (e >= E) return;
    int d = dst[e];
    int pos = atomicAdd(&cnt[d], 1);
    if (pos < CAP) bucket[(size_t)d * CAP + pos] = src[e];
}

__global__ void k_dinv(const int* __restrict__ cnt, float* dinv, int n) {
    int i = blockIdx.x * blockDim.x + threadIdx.x;
    if (i < n) dinv[i] = rsqrtf(1.0f + (float)cnt[i]);   // +1 = self loop
}

// ---------------------------------------------------------------------------
// Layer-1 tf32 GEMM (measured-best R9 config): 128 rows/CTA, B-resident.
// H'[r] = dinv[r] * (X[r] @ W).  W^T staged once (4 chunks); X double-buffered.
// smem 110592 B, 2 CTAs/SM.  A fragments RNA-rounded in-register (raw input).
// ---------------------------------------------------------------------------
#define CLD 36
#define CHUNK (DIM * CLD)                 // 4608 u32
#define GEMM_SMEM_BYTES (6 * CHUNK * 4)   // 110592 B

__global__ void __launch_bounds__(256, 2) k_gemm1(
    const float* __restrict__ X, const float* __restrict__ Bt,
    const float* __restrict__ dinv, float* __restrict__ H, int n) {
    extern __shared__ uint32_t smem[];
    const int tid  = threadIdx.x;
    const int row0 = blockIdx.x * 128;
    const uint32_t sbase = smem_u32(smem);

    auto stage_x = [&](int c) {
        const uint32_t xb = sbase + (uint32_t)(c & 1) * (CHUNK * 4);
        const float4* X4 = (const float4*)X;
#pragma unroll
        for (int i = 0; i < 4; i++) {
            int idx = tid + i * 256;
            int r = idx >> 3, c4 = idx & 7;
            uint32_t off = (uint32_t)(r * CLD + c4 * 4) * 4;
            const float4* xsrc = X4 + ((size_t)(row0 + r) * 32 + c * 8 + c4);
            int vs = (row0 + r < n) ? 16 : 0;
            asm volatile("cp.async.cg.shared.global [%0], [%1], 16, %2;"
                         :: "r"(xb + off), "l"(xsrc), "r"(vs));
        }
    };
    auto stage_b = [&](int c) {
        const uint32_t bb = sbase + (uint32_t)(2 + c) * (CHUNK * 4);
        const float4* B4 = (const float4*)Bt;
#pragma unroll
        for (int i = 0; i < 4; i++) {
            int idx = tid + i * 256;
            int r = idx >> 3, c4 = idx & 7;
            uint32_t off = (uint32_t)(r * CLD + c4 * 4) * 4;
            const float4* bsrc = B4 + ((size_t)r * 32 + c * 8 + c4);
            asm volatile("cp.async.cg.shared.global [%0], [%1], 16;"
                         :: "r"(bb + off), "l"(bsrc));
        }
    };

    stage_b(0); stage_b(1); stage_b(2); stage_b(3);
    stage_x(0);
    asm volatile("cp.async.commit_group;" ::: "memory");
    stage_x(1);
    asm volatile("cp.async.commit_group;" ::: "memory");

    const int warp = tid >> 5;
    const int lane = tid & 31;
    const int wm   = warp & 3;
    const int wn   = warp >> 2;
    const int g    = lane >> 2;
    const int tg   = lane & 3;

    float acc[2][8][4];
#pragma unroll
    for (int mt = 0; mt < 2; mt++)
#pragma unroll
        for (int nt = 0; nt < 8; nt++)
#pragma unroll
            for (int q = 0; q < 4; q++) acc[mt][nt][q] = 0.f;

#pragma unroll
    for (int c = 0; c < 4; c++) {
        if (c < 3) asm volatile("cp.async.wait_group 1;" ::: "memory");
        else       asm volatile("cp.async.wait_group 0;" ::: "memory");
        __syncthreads();

        const uint32_t* Xs = smem + (c & 1) * CHUNK;
        const uint32_t* Ws = smem + (2 + c) * CHUNK;

#pragma unroll
        for (int ks = 0; ks < 4; ks++) {
            const int k0 = ks * 8;
            uint32_t a[2][4];
#pragma unroll
            for (int mt = 0; mt < 2; mt++) {
                int r0 = wm * 32 + mt * 16;
                a[mt][0] = f2tf32(__uint_as_float(Xs[(r0 + g) * CLD + k0 + tg]));
                a[mt][1] = f2tf32(__uint_as_float(Xs[(r0 + 8 + g) * CLD + k0 + tg]));
                a[mt][2] = f2tf32(__uint_as_float(Xs[(r0 + g) * CLD + k0 + tg + 4]));
                a[mt][3] = f2tf32(__uint_as_float(Xs[(r0 + 8 + g) * CLD + k0 + tg + 4]));
            }
#pragma unroll
            for (int nt = 0; nt < 8; nt++) {
                int c0 = wn * 64 + nt * 8;
                uint32_t b0 = Ws[(c0 + g) * CLD + k0 + tg];
                uint32_t b1 = Ws[(c0 + g) * CLD + k0 + tg + 4];
                mma_tf32(acc[0][nt], a[0], b0, b1);
                mma_tf32(acc[1][nt], a[1], b0, b1);
            }
        }
        __syncthreads();
        if (c + 2 < 4) {
            stage_x(c + 2);
            asm volatile("cp.async.commit_group;" ::: "memory");
        }
    }

#pragma unroll
    for (int mt = 0; mt < 2; mt++) {
        int r0 = row0 + wm * 32 + mt * 16 + g;
        int r1 = r0 + 8;
        float dv0 = (r0 < n) ? dinv[r0] : 0.f;
        float dv1 = (r1 < n) ? dinv[r1] : 0.f;
#pragma unroll
        for (int nt = 0; nt < 8; nt++) {
            int col = wn * 64 + nt * 8 + tg * 2;
            if (r0 < n) {
                float2 o = make_float2(acc[mt][nt][0] * dv0, acc[mt][nt][1] * dv0);
                *(float2*)&H[(size_t)r0 * DIM + col] = o;
            }
            if (r1 < n) {
                float2 o = make_float2(acc[mt][nt][2] * dv1, acc[mt][nt][3] * dv1);
                *(float2*)&H[(size_t)r1 * DIM + col] = o;
            }
        }
    }
}

// ---------------------------------------------------------------------------
// FUSED pull + next-layer GEMM.  CTA = 64 dst nodes.
// Phase 1: 8 warps pull 8 nodes each from Hin (gather + self + bias + relu),
//          rna-round, write activations DIRECTLY into smem chunk layout.
//          W^T for the next layer cp.async-staged concurrently.
// Phase 2: tf32 MMA 64x128x128 from smem; Hout[r] = dinv[r]*(act@W).
// smem: act 4 chunks x (64*36) u32 = 36864 B, W 4 chunks x 4608 u32 = 73728 B.
// Total 110592 B, 2 CTAs/SM.
// ---------------------------------------------------------------------------
#define AXCH (64 * CLD)                   // 2304 u32 per act chunk
#define PG_SMEM_BYTES ((4 * AXCH + 4 * CHUNK) * 4)   // 110592 B
#define PG_WOFF (4 * AXCH)                // W base (u32 index)

__global__ void __launch_bounds__(256, 2) k_pullgemm(
    const int* __restrict__ bucket, const int* __restrict__ cnt,
    const float* __restrict__ dinv, const float* __restrict__ Hin,
    const float* __restrict__ bias, const float* __restrict__ Wt,
    float* __restrict__ Hout, int n) {
    extern __shared__ uint32_t smem[];
    const int tid  = threadIdx.x;
    const int warp = tid >> 5;
    const int lane = tid & 31;
    const int row0 = blockIdx.x * 64;
    const uint32_t sbase = smem_u32(smem);

    // Kick off W staging (overlaps the gather phase): 4096 float4, 16/thread.
    {
        const float4* B4 = (const float4*)Wt;
#pragma unroll
        for (int c = 0; c < 4; c++) {
#pragma unroll
            for (int i = 0; i < 4; i++) {
                int idx = tid + i * 256;
                int r = idx >> 3, c4 = idx & 7;
                uint32_t off = (uint32_t)(PG_WOFF + c * CHUNK + r * CLD + c4 * 4) * 4;
                const float4* bsrc = B4 + ((size_t)r * 32 + c * 8 + c4);
                asm volatile("cp.async.cg.shared.global [%0], [%1], 16;"
                             :: "r"(sbase + off), "l"(bsrc));
            }
        }
        asm volatile("cp.async.commit_group;" ::: "memory");
    }

    // Phase 1: pull 8 nodes per warp, write activations into smem chunks.
    const float4* H4 = (const float4*)Hin;
    const float4 bb = ((const float4*)bias)[lane];
    for (int j = 0; j < 8; j++) {
        const int rloc = warp * 8 + j;
        const int v = row0 + rloc;
        uint4 packed = make_uint4(0u, 0u, 0u, 0u);
        if (v < n) {
            int deg = cnt[v];
            if (deg > CAP) deg = CAP;
            const int* bk = bucket + (size_t)v * CAP;

            float4 acc0 = H4[(size_t)v * 32 + lane];   // self-loop
            float4 acc1 = make_float4(0.f, 0.f, 0.f, 0.f);
            float4 acc2 = make_float4(0.f, 0.f, 0.f, 0.f);
            float4 acc3 = make_float4(0.f, 0.f, 0.f, 0.f);

            for (int base = 0; base < deg; base += 32) {
                int m = deg - base; if (m > 32) m = 32;
                int myS = (lane < m) ? bk[base + lane] : 0;
                int i = 0;
                for (; i + 4 <= m; i += 4) {
                    int s0 = __shfl_sync(0xffffffff, myS, i);
                    int s1 = __shfl_sync(0xffffffff, myS, i + 1);
                    int s2 = __shfl_sync(0xffffffff, myS, i + 2);
                    int s3 = __shfl_sync(0xffffffff, myS, i + 3);
                    float4 h0 = H4[(size_t)s0 * 32 + lane];
                    float4 h1 = H4[(size_t)s1 * 32 + lane];
                    float4 h2 = H4[(size_t)s2 * 32 + lane];
                    float4 h3 = H4[(size_t)s3 * 32 + lane];
                    acc0.x += h0.x; acc0.y += h0.y; acc0.z += h0.z; acc0.w += h0.w;
                    acc1.x += h1.x; acc1.y += h1.y; acc1.z += h1.z; acc1.w += h1.w;
                    acc2.x += h2.x; acc2.y += h2.y; acc2.z += h2.z; acc2.w += h2.w;
                    acc3.x += h3.x; acc3.y += h3.y; acc3.z += h3.z; acc3.w += h3.w;
                }
                for (; i < m; i++) {
                    int s0 = __shfl_sync(0xffffffff, myS, i);
                    float4 h0 = H4[(size_t)s0 * 32 + lane];
                    acc0.x += h0.x; acc0.y += h0.y; acc0.z += h0.z; acc0.w += h0.w;
                }
            }
            float dv = dinv[v];
            float sx = (acc0.x + acc1.x) + (acc2.x + acc3.x);
            float sy = (acc0.y + acc1.y) + (acc2.y + acc3.y);
            float sz = (acc0.z + acc1.z) + (acc2.z + acc3.z);
            float sw = (acc0.w + acc1.w) + (acc2.w + acc3.w);
            packed.x = f2tf32(fmaxf(fmaf(sx, dv, bb.x), 0.f));
            packed.y = f2tf32(fmaxf(fmaf(sy, dv, bb.y), 0.f));
            packed.z = f2tf32(fmaxf(fmaf(sz, dv, bb.z), 0.f));
            packed.w = f2tf32(fmaxf(fmaf(sw, dv, bb.w), 0.f));
        }
        // act chunk layout: chunk = lane>>3 (cols 32c..), within = lane&7
        uint32_t idx = (uint32_t)((lane >> 3) * AXCH + rloc * CLD + (lane & 7) * 4);
        *(uint4*)&smem[idx] = packed;
    }

    asm volatile("cp.async.wait_group 0;" ::: "memory");
    __syncthreads();

    // Phase 2: MMA 64x128x128.  wm = warp&1 (2 m-tiles), wn = warp>>1 (4 n-tiles).
    const int wm = warp & 1;
    const int wn = warp >> 1;
    const int g  = lane >> 2;
    const int tg = lane & 3;

    float acc[2][4][4];
#pragma unroll
    for (int mt = 0; mt < 2; mt++)
#pragma unroll
        for (int nt = 0; nt < 4; nt++)
#pragma unroll
            for (int q = 0; q < 4; q++) acc[mt][nt][q] = 0.f;

#pragma unroll
    for (int c = 0; c < 4; c++) {
        const uint32_t* Xs = smem + c * AXCH;
        const uint32_t* Ws = smem + PG_WOFF + c * CHUNK;
#pragma unroll
        for (int ks = 0; ks < 4; ks++) {
            const int k0 = ks * 8;
            uint32_t a[2][4];
#pragma unroll
            for (int mt = 0; mt < 2; mt++) {
                int r0 = wm * 32 + mt * 16;
                a[mt][0] = Xs[(r0 + g) * CLD + k0 + tg];
                a[mt][1] = Xs[(r0 + 8 + g) * CLD + k0 + tg];
                a[mt][2] = Xs[(r0 + g) * CLD + k0 + tg + 4];
                a[mt][3] = Xs[(r0 + 8 + g) * CLD + k0 + tg + 4];
            }
#pragma unroll
            for (int nt = 0; nt < 4; nt++) {
                int c0 = wn * 32 + nt * 8;
                uint32_t b0 = Ws[(c0 + g) * CLD + k0 + tg];
                uint32_t b1 = Ws[(c0 + g) * CLD + k0 + tg + 4];
                mma_tf32(acc[0][nt], a[0], b0, b1);
                mma_tf32(acc[1][nt], a[1], b0, b1);
            }
        }
    }

    // Epilogue: Hout[r] = dinv[r] * acc
#pragma unroll
    for (int mt = 0; mt < 2; mt++) {
        int r0 = row0 + wm * 32 + mt * 16 + g;
        int r1 = r0 + 8;
        float dv0 = (r0 < n) ? dinv[r0] : 0.f;
        float dv1 = (r1 < n) ? dinv[r1] : 0.f;
#pragma unroll
        for (int nt = 0; nt < 4; nt++) {
            int col = wn * 32 + nt * 8 + tg * 2;
            if (r0 < n) {
                float2 o = make_float2(acc[mt][nt][0] * dv0, acc[mt][nt][1] * dv0);
                *(float2*)&Hout[(size_t)r0 * DIM + col] = o;
            }
            if (r1 < n) {
                float2 o = make_float2(acc[mt][nt][2] * dv1, acc[mt][nt][3] * dv1);
                *(float2*)&Hout[(size_t)r1 * DIM + col] = o;
            }
        }
    }
}

// ---------------------------------------------------------------------------
// Final pull (layer 3): OUT[v] = relu(bias + dinv[v]*(H'[v] + sum H'[s]))
// ---------------------------------------------------------------------------
__global__ void k_pull(const int* __restrict__ bucket, const int* __restrict__ cnt,
                       const float* __restrict__ dinv, const float* __restrict__ H,
                       const float* __restrict__ bias, float* __restrict__ OUT, int n) {
    int warp = (blockIdx.x * blockDim.x + threadIdx.x) >> 5;
    int lane = threadIdx.x & 31;
    if (warp >= n) return;
    const int v   = warp;
    int deg = cnt[v];
    if (deg > CAP) deg = CAP;
    const int* bk = bucket + (size_t)v * CAP;
    const float4* H4 = (const float4*)H;

    float4 acc0 = H4[(size_t)v * 32 + lane];
    float4 acc1 = make_float4(0.f, 0.f, 0.f, 0.f);
    float4 acc2 = make_float4(0.f, 0.f, 0.f, 0.f);
    float4 acc3 = make_float4(0.f, 0.f, 0.f, 0.f);

    for (int base = 0; base < deg; base += 32) {
        int m = deg - base; if (m > 32) m = 32;
        int myS = (lane < m) ? bk[base + lane] : 0;
        int i = 0;
        for (; i + 4 <= m; i += 4) {
            int s0 = __shfl_sync(0xffffffff, myS, i);
            int s1 = __shfl_sync(0xffffffff, myS, i + 1);
            int s2 = __shfl_sync(0xffffffff, myS, i + 2);
            int s3 = __shfl_sync(0xffffffff, myS, i + 3);
            float4 h0 = H4[(size_t)s0 * 32 + lane];
            float4 h1 = H4[(size_t)s1 * 32 + lane];
            float4 h2 = H4[(size_t)s2 * 32 + lane];
            float4 h3 = H4[(size_t)s3 * 32 + lane];
            acc0.x += h0.x; acc0.y += h0.y; acc0.z += h0.z; acc0.w += h0.w;
            acc1.x += h1.x; acc1.y += h1.y; acc1.z += h1.z; acc1.w += h1.w;
            acc2.x += h2.x; acc2.y += h2.y; acc2.z += h2.z; acc2.w += h2.w;
            acc3.x += h3.x; acc3.y += h3.y; acc3.z += h3.z; acc3.w += h3.w;
        }
        for (; i < m; i++) {
            int s0 = __shfl_sync(0xffffffff, myS, i);
            float4 h0 = H4[(size_t)s0 * 32 + lane];
            acc0.x += h0.x; acc0.y += h0.y; acc0.z += h0.z; acc0.w += h0.w;
        }
    }

    float dv = dinv[v];
    const float4 bb = ((const float4*)bias)[lane];
    float4 o;
    o.x = fmaxf(fmaf((acc0.x + acc1.x) + (acc2.x + acc3.x), dv, bb.x), 0.f);
    o.y = fmaxf(fmaf((acc0.y + acc1.y) + (acc2.y + acc3.y), dv, bb.y), 0.f);
    o.z = fmaxf(fmaf((acc0.z + acc1.z) + (acc2.z + acc3.z), dv, bb.z), 0.f);
    o.w = fmaxf(fmaf((acc0.w + acc1.w) + (acc2.w + acc3.w), dv, bb.w), 0.f);
    ((float4*)OUT)[(size_t)v * 32 + lane] = o;
}

// ---------------------------------------------------------------------------
// Regressor: pred[t] = A[target[t]] @ Wr[128 x 12] + br
// ---------------------------------------------------------------------------
__global__ void k_regress(const float* __restrict__ H, const int* __restrict__ tgt,
                          const float* __restrict__ Wr, const float* __restrict__ br,
                          float* __restrict__ out, int ntgt) {
    __shared__ float Wrs[DIM * OUTD];
    __shared__ float brs[OUTD];
    int tid = threadIdx.x;
    for (int i = tid; i < DIM * OUTD; i += blockDim.x) Wrs[i] = Wr[i];
    if (tid < OUTD) brs[tid] = br[tid];
    __syncthreads();

    int warp = (blockIdx.x * blockDim.x + tid) >> 5;
    int lane = tid & 31;
    if (warp >= ntgt) return;
    int t = tgt[warp];
    float4 v = ((const float4*)H)[(size_t)t * 32 + lane];
    int k0 = lane * 4;
#pragma unroll
    for (int o = 0; o < OUTD; o++) {
        float p = v.x * Wrs[(k0 + 0) * OUTD + o]
                + v.y * Wrs[(k0 + 1) * OUTD + o]
                + v.z * Wrs[(k0 + 2) * OUTD + o]
                + v.w * Wrs[(k0 + 3) * OUTD + o];
#pragma unroll
        for (int off = 16; off > 0; off >>= 1)
            p += __shfl_xor_sync(0xffffffff, p, off);
        if (lane == 0) out[warp * OUTD + o] = p + brs[o];
    }
}

// ---------------------------------------------------------------------------
// Launch
// ---------------------------------------------------------------------------
extern "C" void kernel_launch(void* const* d_in, const int* in_sizes, int n_in,
                              void* d_out, int out_size) {
    const float* x    = (const float*)d_in[0];
    const int*   ei   = (const int*)d_in[1];
    const int*   tgt  = (const int*)d_in[2];
    const float* W1   = (const float*)d_in[3];
    const float* b1   = (const float*)d_in[4];
    const float* W2   = (const float*)d_in[5];
    const float* b2   = (const float*)d_in[6];
    const float* W3   = (const float*)d_in[7];
    const float* b3   = (const float*)d_in[8];
    const float* Wr   = (const float*)d_in[9];
    const float* br   = (const float*)d_in[10];
    float* out = (float*)d_out;

    const int n    = in_sizes[0] / DIM;
    const int E    = in_sizes[1] / 2;
    const int ntgt = in_sizes[2];
    const int* src = ei;
    const int* dst = ei + E;

    float *H, *B, *A, *Wt, *dinv;
    int *cnt, *bucket;
    cudaGetSymbolAddress((void**)&H,      g_H);
    cudaGetSymbolAddress((void**)&B,      g_B);
    cudaGetSymbolAddress((void**)&A,      g_A);
    cudaGetSymbolAddress((void**)&Wt,     g_Wt);
    cudaGetSymbolAddress((void**)&dinv,   g_dinv);
    cudaGetSymbolAddress((void**)&cnt,    g_cnt);
    cudaGetSymbolAddress((void**)&bucket, g_bucket);

    cudaFuncSetAttribute(k_gemm1, cudaFuncAttributeMaxDynamicSharedMemorySize,
                         GEMM_SMEM_BYTES);
    cudaFuncSetAttribute(k_pullgemm, cudaFuncAttributeMaxDynamicSharedMemorySize,
                         PG_SMEM_BYTES);

    const int TPB = 256;
    const int nBlk    = (n + TPB - 1) / TPB;
    const int eBlk    = (E + TPB - 1) / TPB;
    const int gemmBlk = (n + 127) / 128;
    const int pgBlk   = (n + 63) / 64;
    const int pullBlk = ((n * 32) + TPB - 1) / TPB;
    const int regBlk  = ((ntgt * 32) + TPB - 1) / TPB;

    // Precompute: weights transpose+round + cnt zero (fused), buckets, dinv
    k_pre<<<48 + nBlk, TPB>>>(W1, W2, W3, Wt, cnt, n);
    k_fill<<<eBlk, TPB>>>(src, dst, cnt, bucket, E);
    k_dinv<<<nBlk, TPB>>>(cnt, dinv, n);

    // Layer 1 GEMM: x -> H (dinv-scaled)
    k_gemm1<<<gemmBlk, 256, GEMM_SMEM_BYTES>>>(x, Wt, dinv, H, n);

    // Fused pull(1)+GEMM(2): H -> B
    k_pullgemm<<<pgBlk, 256, PG_SMEM_BYTES>>>(bucket, cnt, dinv, H, b1,
                                              Wt + DIM * DIM, B, n);
    // Fused pull(2)+GEMM(3): B -> H
    k_pullgemm<<<pgBlk, 256, PG_SMEM_BYTES>>>(bucket, cnt, dinv, B, b2,
                                              Wt + 2 * DIM * DIM, H, n);
    // Final pull(3): H -> A
    k_pull<<<pullBlk, TPB>>>(bucket, cnt, dinv, H, b3, A, n);

    // Regressor on targets
    k_regress<<<regBlk, TPB>>>(A, tgt, Wr, br, out, ntgt);
}

// round 14
// speedup vs baseline: 1.1979x; 1.1979x over previous
#include <cuda_runtime.h>
#include <cuda_bf16.h>
#include <cstdint>

// Problem constants (fixed by the dataset)
#define N_NODES 50000
#define N_EDGES 800000
#define DIM     128
#define OUTD    12
#define CAP     128          // per-node in-edge bucket capacity (Poisson(16) degree)

// ---------------------------------------------------------------------------
// Device scratch (no allocations allowed)
// ---------------------------------------------------------------------------
__device__ float g_H[N_NODES * DIM];        // GEMM output, pre-scaled by dinv
__device__ float g_A[N_NODES * DIM];        // ping (tf32-rounded activations)
__device__ float g_B[N_NODES * DIM];        // pong
__device__ float g_Wt[3 * DIM * DIM];       // transposed + tf32-rounded weights
__device__ int   g_cnt[N_NODES];
__device__ int   g_bucket[N_NODES * CAP];   // in-edge src lists per dst

__device__ __forceinline__ uint32_t f2tf32(float f) {
    uint32_t u;
    asm("cvt.rna.tf32.f32 %0, %1;" : "=r"(u) : "f"(f));
    return u;
}

__device__ __forceinline__ uint32_t smem_u32(const void* p) {
    uint32_t a;
    asm("{ .reg .u64 t; cvta.to.shared.u64 t, %1; cvt.u32.u64 %0, t; }" : "=r"(a) : "l"(p));
    return a;
}

__device__ __forceinline__ void mma_tf32(float* d, const uint32_t* a,
                                         uint32_t b0, uint32_t b1) {
    asm volatile(
        "mma.sync.aligned.m16n8k8.row.col.f32.tf32.tf32.f32 "
        "{%0,%1,%2,%3}, {%4,%5,%6,%7}, {%8,%9}, {%0,%1,%2,%3};"
        : "+f"(d[0]), "+f"(d[1]), "+f"(d[2]), "+f"(d[3])
        : "r"(a[0]), "r"(a[1]), "r"(a[2]), "r"(a[3]), "r"(b0), "r"(b1));
}

// ---------------------------------------------------------------------------
// Fused precompute: blocks 0..47 transpose+round weights, rest zero cnt.
// ---------------------------------------------------------------------------
__global__ void k_pre(const float* __restrict__ W1, const float* __restrict__ W2,
                      const float* __restrict__ W3, float* __restrict__ Wt,
                      int* __restrict__ cnt, int n) {
    int b = blockIdx.x;
    int t = threadIdx.x;
    if (b < 48) {
        __shared__ float tile[32][33];
        int bz = b >> 4, rem = b & 15, bx = rem & 3, by = rem >> 2;
        const float* W = (bz == 0) ? W1 : (bz == 1) ? W2 : W3;
        float* dst = Wt + (size_t)bz * DIM * DIM;
        int tx = t & 31, ty = t >> 5;
        int x = bx * 32 + tx, y = by * 32 + ty;
#pragma unroll
        for (int j = 0; j < 32; j += 8)
            tile[ty + j][tx] = W[(y + j) * DIM + x];
        __syncthreads();
        x = by * 32 + tx; y = bx * 32 + ty;
#pragma unroll
        for (int j = 0; j < 32; j += 8)
            dst[(y + j) * DIM + x] = __uint_as_float(f2tf32(tile[tx][ty + j]));
    } else {
        int i = (b - 48) * 256 + t;
        if (i < n) cnt[i] = 0;
    }
}

__global__ void k_fill(const int* __restrict__ src, const int* __restrict__ dst,
                       int* cnt, int* bucket, int E) {
    int e = blockIdx.x * blockDim.x + threadIdx.x;
    if (e >= E) return;
    int d = dst[e];
    int pos = atomicAdd(&cnt[d], 1);
    if (pos < CAP) bucket[(size_t)d * CAP + pos] = src[e];
}

// ---------------------------------------------------------------------------
// tf32 tensor-core GEMM, 128x128 tile, B-resident, 512 threads (16 warps).
// H'[r] = rsqrt(1+cnt[r]) * (X[r] @ W).  W^T staged once; X double-buffered.
// smem 110592 B, 2 CTAs/SM -> 32 warps/SM for latency hiding.
// Warp tile 32x32 (4x4 warp grid); acc 32 regs/thread.
// CVTA=true: RNA-round A fragments in-register (layer 1 only).
// ---------------------------------------------------------------------------
#define CLD 36
#define CHUNK (DIM * CLD)                 // 4608 u32
#define GEMM_SMEM_BYTES (6 * CHUNK * 4)   // 110592 B

template <bool CVTA>
__global__ void __launch_bounds__(512, 2) k_gemm_tc(
    const float* __restrict__ X, const float* __restrict__ Bt,
    const int* __restrict__ cnt, float* __restrict__ H, int n) {
    extern __shared__ uint32_t smem[];
    const int tid  = threadIdx.x;
    const int row0 = blockIdx.x * 128;
    const uint32_t sbase = smem_u32(smem);

    // Stage X K-chunk c into buffer c&1 (1024 float4 over 512 threads).
    auto stage_x = [&](int c) {
        const uint32_t xb = sbase + (uint32_t)(c & 1) * (CHUNK * 4);
        const float4* X4 = (const float4*)X;
#pragma unroll
        for (int i = 0; i < 2; i++) {
            int idx = tid + i * 512;
            int r = idx >> 3, c4 = idx & 7;
            uint32_t off = (uint32_t)(r * CLD + c4 * 4) * 4;
            const float4* xsrc = X4 + ((size_t)(row0 + r) * 32 + c * 8 + c4);
            int vs = (row0 + r < n) ? 16 : 0;
            asm volatile("cp.async.cg.shared.global [%0], [%1], 16, %2;"
                         :: "r"(xb + off), "l"(xsrc), "r"(vs));
        }
    };
    // Stage B K-chunk c into resident slot 2+c.
    auto stage_b = [&](int c) {
        const uint32_t bb = sbase + (uint32_t)(2 + c) * (CHUNK * 4);
        const float4* B4 = (const float4*)Bt;
#pragma unroll
        for (int i = 0; i < 2; i++) {
            int idx = tid + i * 512;
            int r = idx >> 3, c4 = idx & 7;
            uint32_t off = (uint32_t)(r * CLD + c4 * 4) * 4;
            const float4* bsrc = B4 + ((size_t)r * 32 + c * 8 + c4);
            asm volatile("cp.async.cg.shared.global [%0], [%1], 16;"
                         :: "r"(bb + off), "l"(bsrc));
        }
    };

    stage_b(0); stage_b(1); stage_b(2); stage_b(3);
    stage_x(0);
    asm volatile("cp.async.commit_group;" ::: "memory");
    stage_x(1);
    asm volatile("cp.async.commit_group;" ::: "memory");

    const int warp = tid >> 5;
    const int lane = tid & 31;
    const int wm   = warp & 3;        // m-tile: rows wm*32 .. +31
    const int wn   = warp >> 2;       // n-tile: cols wn*32 .. +31
    const int g    = lane >> 2;
    const int tg   = lane & 3;

    float acc[2][4][4];
#pragma unroll
    for (int mt = 0; mt < 2; mt++)
#pragma unroll
        for (int nt = 0; nt < 4; nt++)
#pragma unroll
            for (int q = 0; q < 4; q++) acc[mt][nt][q] = 0.f;

#pragma unroll
    for (int c = 0; c < 4; c++) {
        if (c < 3) asm volatile("cp.async.wait_group 1;" ::: "memory");
        else       asm volatile("cp.async.wait_group 0;" ::: "memory");
        __syncthreads();

        const uint32_t* Xs = smem + (c & 1) * CHUNK;
        const uint32_t* Ws = smem + (2 + c) * CHUNK;

#pragma unroll
        for (int ks = 0; ks < 4; ks++) {
            const int k0 = ks * 8;
            uint32_t a[2][4];
#pragma unroll
            for (int mt = 0; mt < 2; mt++) {
                int r0 = wm * 32 + mt * 16;
                a[mt][0] = Xs[(r0 + g) * CLD + k0 + tg];
                a[mt][1] = Xs[(r0 + 8 + g) * CLD + k0 + tg];
                a[mt][2] = Xs[(r0 + g) * CLD + k0 + tg + 4];
                a[mt][3] = Xs[(r0 + 8 + g) * CLD + k0 + tg + 4];
                if (CVTA) {
#pragma unroll
                    for (int q = 0; q < 4; q++)
                        a[mt][q] = f2tf32(__uint_as_float(a[mt][q]));
                }
            }
#pragma unroll
            for (int nt = 0; nt < 4; nt++) {
                int c0 = wn * 32 + nt * 8;
                uint32_t b0 = Ws[(c0 + g) * CLD + k0 + tg];
                uint32_t b1 = Ws[(c0 + g) * CLD + k0 + tg + 4];
                mma_tf32(acc[0][nt], a[0], b0, b1);
                mma_tf32(acc[1][nt], a[1], b0, b1);
            }
        }
        __syncthreads();
        if (c + 2 < 4) {
            stage_x(c + 2);
            asm volatile("cp.async.commit_group;" ::: "memory");
        }
    }

    // Epilogue: scale by rsqrt(1+cnt[row]), float2 stores.
#pragma unroll
    for (int mt = 0; mt < 2; mt++) {
        int r0 = row0 + wm * 32 + mt * 16 + g;
        int r1 = r0 + 8;
        float dv0 = (r0 < n) ? rsqrtf(1.0f + (float)cnt[r0]) : 0.f;
        float dv1 = (r1 < n) ? rsqrtf(1.0f + (float)cnt[r1]) : 0.f;
#pragma unroll
        for (int nt = 0; nt < 4; nt++) {
            int col = wn * 32 + nt * 8 + tg * 2;
            if (r0 < n) {
                float2 o = make_float2(acc[mt][nt][0] * dv0, acc[mt][nt][1] * dv0);
                *(float2*)&H[(size_t)r0 * DIM + col] = o;
            }
            if (r1 < n) {
                float2 o = make_float2(acc[mt][nt][2] * dv1, acc[mt][nt][3] * dv1);
                *(float2*)&H[(size_t)r1 * DIM + col] = o;
            }
        }
    }
}

// ---------------------------------------------------------------------------
// Pull aggregation: one warp per destination node, fp32, 4-way ILP.
// OUT[v] = rna_tf32(relu(bias + dinv[v] * (H'[v] + sum_{s in in(v)} H'[s])))
// dinv computed inline from cnt.
// ---------------------------------------------------------------------------
__global__ void k_pull(const int* __restrict__ bucket, const int* __restrict__ cnt,
                       const float* __restrict__ H,
                       const float* __restrict__ bias, float* __restrict__ OUT, int n) {
    int warp = (blockIdx.x * blockDim.x + threadIdx.x) >> 5;
    int lane = threadIdx.x & 31;
    if (warp >= n) return;
    const int v = warp;
    int rawdeg = cnt[v];
    int deg = rawdeg > CAP ? CAP : rawdeg;
    const int* bk = bucket + (size_t)v * CAP;
    const float4* H4 = (const float4*)H;

    float4 acc0 = H4[(size_t)v * 32 + lane];   // self-loop term
    float4 acc1 = make_float4(0.f, 0.f, 0.f, 0.f);
    float4 acc2 = make_float4(0.f, 0.f, 0.f, 0.f);
    float4 acc3 = make_float4(0.f, 0.f, 0.f, 0.f);

    for (int base = 0; base < deg; base += 32) {
        int m = deg - base; if (m > 32) m = 32;
        int myS = (lane < m) ? bk[base + lane] : 0;
        int i = 0;
        for (; i + 4 <= m; i += 4) {
            int s0 = __shfl_sync(0xffffffff, myS, i);
            int s1 = __shfl_sync(0xffffffff, myS, i + 1);
            int s2 = __shfl_sync(0xffffffff, myS, i + 2);
            int s3 = __shfl_sync(0xffffffff, myS, i + 3);
            float4 h0 = H4[(size_t)s0 * 32 + lane];
            float4 h1 = H4[(size_t)s1 * 32 + lane];
            float4 h2 = H4[(size_t)s2 * 32 + lane];
            float4 h3 = H4[(size_t)s3 * 32 + lane];
            acc0.x += h0.x; acc0.y += h0.y; acc0.z += h0.z; acc0.w += h0.w;
            acc1.x += h1.x; acc1.y += h1.y; acc1.z += h1.z; acc1.w += h1.w;
            acc2.x += h2.x; acc2.y += h2.y; acc2.z += h2.z; acc2.w += h2.w;
            acc3.x += h3.x; acc3.y += h3.y; acc3.z += h3.z; acc3.w += h3.w;
        }
        for (; i < m; i++) {
            int s0 = __shfl_sync(0xffffffff, myS, i);
            float4 h0 = H4[(size_t)s0 * 32 + lane];
            acc0.x += h0.x; acc0.y += h0.y; acc0.z += h0.z; acc0.w += h0.w;
        }
    }

    float dv = rsqrtf(1.0f + (float)rawdeg);
    const float4 bb = ((const float4*)bias)[lane];
    float sx = (acc0.x + acc1.x) + (acc2.x + acc3.x);
    float sy = (acc0.y + acc1.y) + (acc2.y + acc3.y);
    float sz = (acc0.z + acc1.z) + (acc2.z + acc3.z);
    float sw = (acc0.w + acc1.w) + (acc2.w + acc3.w);
    float4 o;
    o.x = __uint_as_float(f2tf32(fmaxf(fmaf(sx, dv, bb.x), 0.f)));
    o.y = __uint_as_float(f2tf32(fmaxf(fmaf(sy, dv, bb.y), 0.f)));
    o.z = __uint_as_float(f2tf32(fmaxf(fmaf(sz, dv, bb.z), 0.f)));
    o.w = __uint_as_float(f2tf32(fmaxf(fmaf(sw, dv, bb.w), 0.f)));
    ((float4*)OUT)[(size_t)v * 32 + lane] = o;
}

// ---------------------------------------------------------------------------
// Regressor: pred[t] = A[target[t]] @ Wr[128 x 12] + br   (A already relu'd)
// ---------------------------------------------------------------------------
__global__ void k_regress(const float* __restrict__ H, const int* __restrict__ tgt,
                          const float* __restrict__ Wr, const float* __restrict__ br,
                          float* __restrict__ out, int ntgt) {
    __shared__ float Wrs[DIM * OUTD];
    __shared__ float brs[OUTD];
    int tid = threadIdx.x;
    for (int i = tid; i < DIM * OUTD; i += blockDim.x) Wrs[i] = Wr[i];
    if (tid < OUTD) brs[tid] = br[tid];
    __syncthreads();

    int warp = (blockIdx.x * blockDim.x + tid) >> 5;
    int lane = tid & 31;
    if (warp >= ntgt) return;
    int t = tgt[warp];
    float4 v = ((const float4*)H)[(size_t)t * 32 + lane];
    int k0 = lane * 4;
#pragma unroll
    for (int o = 0; o < OUTD; o++) {
        float p = v.x * Wrs[(k0 + 0) * OUTD + o]
                + v.y * Wrs[(k0 + 1) * OUTD + o]
                + v.z * Wrs[(k0 + 2) * OUTD + o]
                + v.w * Wrs[(k0 + 3) * OUTD + o];
#pragma unroll
        for (int off = 16; off > 0; off >>= 1)
            p += __shfl_xor_sync(0xffffffff, p, off);
        if (lane == 0) out[warp * OUTD + o] = p + brs[o];
    }
}

// ---------------------------------------------------------------------------
// Launch
// ---------------------------------------------------------------------------
extern "C" void kernel_launch(void* const* d_in, const int* in_sizes, int n_in,
                              void* d_out, int out_size) {
    const float* x    = (const float*)d_in[0];
    const int*   ei   = (const int*)d_in[1];
    const int*   tgt  = (const int*)d_in[2];
    const float* W1   = (const float*)d_in[3];
    const float* b1   = (const float*)d_in[4];
    const float* W2   = (const float*)d_in[5];
    const float* b2   = (const float*)d_in[6];
    const float* W3   = (const float*)d_in[7];
    const float* b3   = (const float*)d_in[8];
    const float* Wr   = (const float*)d_in[9];
    const float* br   = (const float*)d_in[10];
    float* out = (float*)d_out;

    const int n    = in_sizes[0] / DIM;
    const int E    = in_sizes[1] / 2;
    const int ntgt = in_sizes[2];
    const int* src = ei;
    const int* dst = ei + E;

    float *H, *A, *B, *Wt;
    int *cnt, *bucket;
    cudaGetSymbolAddress((void**)&H,      g_H);
    cudaGetSymbolAddress((void**)&A,      g_A);
    cudaGetSymbolAddress((void**)&B,      g_B);
    cudaGetSymbolAddress((void**)&Wt,     g_Wt);
    cudaGetSymbolAddress((void**)&cnt,    g_cnt);
    cudaGetSymbolAddress((void**)&bucket, g_bucket);

    cudaFuncSetAttribute(k_gemm_tc<true>, cudaFuncAttributeMaxDynamicSharedMemorySize,
                         GEMM_SMEM_BYTES);
    cudaFuncSetAttribute(k_gemm_tc<false>, cudaFuncAttributeMaxDynamicSharedMemorySize,
                         GEMM_SMEM_BYTES);

    const int TPB = 256;
    const int nBlk    = (n + TPB - 1) / TPB;
    const int eBlk    = (E + TPB - 1) / TPB;
    const int gemmBlk = (n + 127) / 128;
    const int pullBlk = ((n * 32) + TPB - 1) / TPB;
    const int regBlk  = ((ntgt * 32) + TPB - 1) / TPB;

    // 1: transpose+round weights, zero counts (fused); 2: buckets
    k_pre<<<48 + nBlk, TPB>>>(W1, W2, W3, Wt, cnt, n);
    k_fill<<<eBlk, TPB>>>(src, dst, cnt, bucket, E);

    // Conv 1: x -> A
    k_gemm_tc<true><<<gemmBlk, 512, GEMM_SMEM_BYTES>>>(x, Wt, cnt, H, n);
    k_pull<<<pullBlk, TPB>>>(bucket, cnt, H, b1, A, n);

    // Conv 2: A -> B
    k_gemm_tc<false><<<gemmBlk, 512, GEMM_SMEM_BYTES>>>(A, Wt + DIM * DIM, cnt, H, n);
    k_pull<<<pullBlk, TPB>>>(bucket, cnt, H, b2, B, n);

    // Conv 3: B -> A
    k_gemm_tc<false><<<gemmBlk, 512, GEMM_SMEM_BYTES>>>(B, Wt + 2 * DIM * DIM, cnt, H, n);
    k_pull<<<pullBlk, TPB>>>(bucket, cnt, H, b3, A, n);

    // Regressor on targets
    k_regress<<<regBlk, TPB>>>(A, tgt, Wr, br, out, ntgt);
}

// round 15
// speedup vs baseline: 1.4557x; 1.2152x over previous
#include <cuda_runtime.h>
#include <cuda_bf16.h>
#include <cstdint>

// Problem constants (fixed by the dataset)
#define N_NODES 50000
#define N_EDGES 800000
#define DIM     128
#define OUTD    12
#define CAP     128          // per-node in-edge bucket capacity (Poisson(16) degree)

// ---------------------------------------------------------------------------
// Device scratch (no allocations allowed)
// ---------------------------------------------------------------------------
__device__ float g_H[N_NODES * DIM];        // GEMM output, pre-scaled by dinv
__device__ float g_A[N_NODES * DIM];        // ping (tf32-rounded activations)
__device__ float g_B[N_NODES * DIM];        // pong
__device__ float g_Wt[3 * DIM * DIM];       // transposed + tf32-rounded weights
__device__ int   g_cnt[N_NODES];
__device__ int   g_bucket[N_NODES * CAP];   // in-edge src lists per dst

__device__ __forceinline__ uint32_t f2tf32(float f) {
    uint32_t u;
    asm("cvt.rna.tf32.f32 %0, %1;" : "=r"(u) : "f"(f));
    return u;
}

__device__ __forceinline__ uint32_t smem_u32(const void* p) {
    uint32_t a;
    asm("{ .reg .u64 t; cvta.to.shared.u64 t, %1; cvt.u32.u64 %0, t; }" : "=r"(a) : "l"(p));
    return a;
}

__device__ __forceinline__ void mma_tf32(float* d, const uint32_t* a,
                                         uint32_t b0, uint32_t b1) {
    asm volatile(
        "mma.sync.aligned.m16n8k8.row.col.f32.tf32.tf32.f32 "
        "{%0,%1,%2,%3}, {%4,%5,%6,%7}, {%8,%9}, {%0,%1,%2,%3};"
        : "+f"(d[0]), "+f"(d[1]), "+f"(d[2]), "+f"(d[3])
        : "r"(a[0]), "r"(a[1]), "r"(a[2]), "r"(a[3]), "r"(b0), "r"(b1));
}

// ---------------------------------------------------------------------------
// Fused precompute: blocks 0..47 transpose+round weights, rest zero cnt.
// ---------------------------------------------------------------------------
__global__ void k_pre(const float* __restrict__ W1, const float* __restrict__ W2,
                      const float* __restrict__ W3, float* __restrict__ Wt,
                      int* __restrict__ cnt, int n) {
    int b = blockIdx.x;
    int t = threadIdx.x;
    if (b < 48) {
        __shared__ float tile[32][33];
        int bz = b >> 4, rem = b & 15, bx = rem & 3, by = rem >> 2;
        const float* W = (bz == 0) ? W1 : (bz == 1) ? W2 : W3;
        float* dst = Wt + (size_t)bz * DIM * DIM;
        int tx = t & 31, ty = t >> 5;
        int x = bx * 32 + tx, y = by * 32 + ty;
#pragma unroll
        for (int j = 0; j < 32; j += 8)
            tile[ty + j][tx] = W[(y + j) * DIM + x];
        __syncthreads();
        x = by * 32 + tx; y = bx * 32 + ty;
#pragma unroll
        for (int j = 0; j < 32; j += 8)
            dst[(y + j) * DIM + x] = __uint_as_float(f2tf32(tile[tx][ty + j]));
    } else {
        int i = (b - 48) * 256 + t;
        if (i < n) cnt[i] = 0;
    }
}

__global__ void k_fill(const int* __restrict__ src, const int* __restrict__ dst,
                       int* cnt, int* bucket, int E) {
    int e = blockIdx.x * blockDim.x + threadIdx.x;
    if (e >= E) return;
    int d = dst[e];
    int pos = atomicAdd(&cnt[d], 1);
    if (pos < CAP) bucket[(size_t)d * CAP + pos] = src[e];
}

// ---------------------------------------------------------------------------
// tf32 tensor-core GEMM (measured-best R9 shape): 128x128 tile, 256 threads,
// B-resident (W^T staged once, 4 chunks), X double-buffered.
// H'[r] = rsqrt(1+cnt[r]) * (X[r] @ W).  smem 110592 B, 2 CTAs/SM.
// CVTA=true: RNA-round A fragments in-register (layer 1 only).
// ---------------------------------------------------------------------------
#define CLD 36
#define CHUNK (DIM * CLD)                 // 4608 u32
#define GEMM_SMEM_BYTES (6 * CHUNK * 4)   // 110592 B

template <bool CVTA>
__global__ void __launch_bounds__(256, 2) k_gemm_tc(
    const float* __restrict__ X, const float* __restrict__ Bt,
    const int* __restrict__ cnt, float* __restrict__ H, int n) {
    extern __shared__ uint32_t smem[];
    const int tid  = threadIdx.x;
    const int row0 = blockIdx.x * 128;
    const uint32_t sbase = smem_u32(smem);

    auto stage_x = [&](int c) {
        const uint32_t xb = sbase + (uint32_t)(c & 1) * (CHUNK * 4);
        const float4* X4 = (const float4*)X;
#pragma unroll
        for (int i = 0; i < 4; i++) {
            int idx = tid + i * 256;
            int r = idx >> 3, c4 = idx & 7;
            uint32_t off = (uint32_t)(r * CLD + c4 * 4) * 4;
            const float4* xsrc = X4 + ((size_t)(row0 + r) * 32 + c * 8 + c4);
            int vs = (row0 + r < n) ? 16 : 0;
            asm volatile("cp.async.cg.shared.global [%0], [%1], 16, %2;"
                         :: "r"(xb + off), "l"(xsrc), "r"(vs));
        }
    };
    auto stage_b = [&](int c) {
        const uint32_t bb = sbase + (uint32_t)(2 + c) * (CHUNK * 4);
        const float4* B4 = (const float4*)Bt;
#pragma unroll
        for (int i = 0; i < 4; i++) {
            int idx = tid + i * 256;
            int r = idx >> 3, c4 = idx & 7;
            uint32_t off = (uint32_t)(r * CLD + c4 * 4) * 4;
            const float4* bsrc = B4 + ((size_t)r * 32 + c * 8 + c4);
            asm volatile("cp.async.cg.shared.global [%0], [%1], 16;"
                         :: "r"(bb + off), "l"(bsrc));
        }
    };

    stage_b(0); stage_b(1); stage_b(2); stage_b(3);
    stage_x(0);
    asm volatile("cp.async.commit_group;" ::: "memory");
    stage_x(1);
    asm volatile("cp.async.commit_group;" ::: "memory");

    const int warp = tid >> 5;
    const int lane = tid & 31;
    const int wm   = warp & 3;
    const int wn   = warp >> 2;
    const int g    = lane >> 2;
    const int tg   = lane & 3;

    float acc[2][8][4];
#pragma unroll
    for (int mt = 0; mt < 2; mt++)
#pragma unroll
        for (int nt = 0; nt < 8; nt++)
#pragma unroll
            for (int q = 0; q < 4; q++) acc[mt][nt][q] = 0.f;

#pragma unroll
    for (int c = 0; c < 4; c++) {
        if (c < 3) asm volatile("cp.async.wait_group 1;" ::: "memory");
        else       asm volatile("cp.async.wait_group 0;" ::: "memory");
        __syncthreads();

        const uint32_t* Xs = smem + (c & 1) * CHUNK;
        const uint32_t* Ws = smem + (2 + c) * CHUNK;

#pragma unroll
        for (int ks = 0; ks < 4; ks++) {
            const int k0 = ks * 8;
            uint32_t a[2][4];
#pragma unroll
            for (int mt = 0; mt < 2; mt++) {
                int r0 = wm * 32 + mt * 16;
                a[mt][0] = Xs[(r0 + g) * CLD + k0 + tg];
                a[mt][1] = Xs[(r0 + 8 + g) * CLD + k0 + tg];
                a[mt][2] = Xs[(r0 + g) * CLD + k0 + tg + 4];
                a[mt][3] = Xs[(r0 + 8 + g) * CLD + k0 + tg + 4];
                if (CVTA) {
#pragma unroll
                    for (int q = 0; q < 4; q++)
                        a[mt][q] = f2tf32(__uint_as_float(a[mt][q]));
                }
            }
#pragma unroll
            for (int nt = 0; nt < 8; nt++) {
                int c0 = wn * 64 + nt * 8;
                uint32_t b0 = Ws[(c0 + g) * CLD + k0 + tg];
                uint32_t b1 = Ws[(c0 + g) * CLD + k0 + tg + 4];
                mma_tf32(acc[0][nt], a[0], b0, b1);
                mma_tf32(acc[1][nt], a[1], b0, b1);
            }
        }
        __syncthreads();
        if (c + 2 < 4) {
            stage_x(c + 2);
            asm volatile("cp.async.commit_group;" ::: "memory");
        }
    }

    // Epilogue: scale by rsqrt(1+cnt[row]), float2 stores.
#pragma unroll
    for (int mt = 0; mt < 2; mt++) {
        int r0 = row0 + wm * 32 + mt * 16 + g;
        int r1 = r0 + 8;
        float dv0 = (r0 < n) ? rsqrtf(1.0f + (float)cnt[r0]) : 0.f;
        float dv1 = (r1 < n) ? rsqrtf(1.0f + (float)cnt[r1]) : 0.f;
#pragma unroll
        for (int nt = 0; nt < 8; nt++) {
            int col = wn * 64 + nt * 8 + tg * 2;
            if (r0 < n) {
                float2 o = make_float2(acc[mt][nt][0] * dv0, acc[mt][nt][1] * dv0);
                *(float2*)&H[(size_t)r0 * DIM + col] = o;
            }
            if (r1 < n) {
                float2 o = make_float2(acc[mt][nt][2] * dv1, acc[mt][nt][3] * dv1);
                *(float2*)&H[(size_t)r1 * DIM + col] = o;
            }
        }
    }
}

// ---------------------------------------------------------------------------
// Pull aggregation (layers 1-2): one warp per destination node.
// OUT[v] = rna_tf32(relu(bias + dinv[v] * (H'[v] + sum_{s in in(v)} H'[s])))
// ---------------------------------------------------------------------------
__global__ void k_pull(const int* __restrict__ bucket, const int* __restrict__ cnt,
                       const float* __restrict__ H,
                       const float* __restrict__ bias, float* __restrict__ OUT, int n) {
    int warp = (blockIdx.x * blockDim.x + threadIdx.x) >> 5;
    int lane = threadIdx.x & 31;
    if (warp >= n) return;
    const int v = warp;
    int rawdeg = cnt[v];
    int deg = rawdeg > CAP ? CAP : rawdeg;
    const int* bk = bucket + (size_t)v * CAP;
    const float4* H4 = (const float4*)H;

    float4 acc0 = H4[(size_t)v * 32 + lane];   // self-loop term
    float4 acc1 = make_float4(0.f, 0.f, 0.f, 0.f);
    float4 acc2 = make_float4(0.f, 0.f, 0.f, 0.f);
    float4 acc3 = make_float4(0.f, 0.f, 0.f, 0.f);

    for (int base = 0; base < deg; base += 32) {
        int m = deg - base; if (m > 32) m = 32;
        int myS = (lane < m) ? bk[base + lane] : 0;
        int i = 0;
        for (; i + 4 <= m; i += 4) {
            int s0 = __shfl_sync(0xffffffff, myS, i);
            int s1 = __shfl_sync(0xffffffff, myS, i + 1);
            int s2 = __shfl_sync(0xffffffff, myS, i + 2);
            int s3 = __shfl_sync(0xffffffff, myS, i + 3);
            float4 h0 = H4[(size_t)s0 * 32 + lane];
            float4 h1 = H4[(size_t)s1 * 32 + lane];
            float4 h2 = H4[(size_t)s2 * 32 + lane];
            float4 h3 = H4[(size_t)s3 * 32 + lane];
            acc0.x += h0.x; acc0.y += h0.y; acc0.z += h0.z; acc0.w += h0.w;
            acc1.x += h1.x; acc1.y += h1.y; acc1.z += h1.z; acc1.w += h1.w;
            acc2.x += h2.x; acc2.y += h2.y; acc2.z += h2.z; acc2.w += h2.w;
            acc3.x += h3.x; acc3.y += h3.y; acc3.z += h3.z; acc3.w += h3.w;
        }
        for (; i < m; i++) {
            int s0 = __shfl_sync(0xffffffff, myS, i);
            float4 h0 = H4[(size_t)s0 * 32 + lane];
            acc0.x += h0.x; acc0.y += h0.y; acc0.z += h0.z; acc0.w += h0.w;
        }
    }

    float dv = rsqrtf(1.0f + (float)rawdeg);
    const float4 bb = ((const float4*)bias)[lane];
    float sx = (acc0.x + acc1.x) + (acc2.x + acc3.x);
    float sy = (acc0.y + acc1.y) + (acc2.y + acc3.y);
    float sz = (acc0.z + acc1.z) + (acc2.z + acc3.z);
    float sw = (acc0.w + acc1.w) + (acc2.w + acc3.w);
    float4 o;
    o.x = __uint_as_float(f2tf32(fmaxf(fmaf(sx, dv, bb.x), 0.f)));
    o.y = __uint_as_float(f2tf32(fmaxf(fmaf(sy, dv, bb.y), 0.f)));
    o.z = __uint_as_float(f2tf32(fmaxf(fmaf(sz, dv, bb.z), 0.f)));
    o.w = __uint_as_float(f2tf32(fmaxf(fmaf(sw, dv, bb.w), 0.f)));
    ((float4*)OUT)[(size_t)v * 32 + lane] = o;
}

// ---------------------------------------------------------------------------
// FUSED final pull + regressor: only the 8192 TARGET nodes are aggregated.
// One warp per target t: v=tgt[t]; s = relu(b3 + dinv[v]*(H'[v]+sum H'[src]));
// out[t] = s @ Wr + br   (12 warp-reduced dot products, Wr in smem).
// ---------------------------------------------------------------------------
__global__ void k_pull_regress(
    const int* __restrict__ bucket, const int* __restrict__ cnt,
    const float* __restrict__ H, const float* __restrict__ bias,
    const int* __restrict__ tgt, const float* __restrict__ Wr,
    const float* __restrict__ br, float* __restrict__ out, int ntgt) {
    __shared__ float Wrs[DIM * OUTD];
    __shared__ float brs[OUTD];
    int tid = threadIdx.x;
    for (int i = tid; i < DIM * OUTD; i += blockDim.x) Wrs[i] = Wr[i];
    if (tid < OUTD) brs[tid] = br[tid];
    __syncthreads();

    int warp = (blockIdx.x * blockDim.x + tid) >> 5;
    int lane = tid & 31;
    if (warp >= ntgt) return;
    const int v = tgt[warp];
    int rawdeg = cnt[v];
    int deg = rawdeg > CAP ? CAP : rawdeg;
    const int* bk = bucket + (size_t)v * CAP;
    const float4* H4 = (const float4*)H;

    float4 acc0 = H4[(size_t)v * 32 + lane];   // self-loop term
    float4 acc1 = make_float4(0.f, 0.f, 0.f, 0.f);
    float4 acc2 = make_float4(0.f, 0.f, 0.f, 0.f);
    float4 acc3 = make_float4(0.f, 0.f, 0.f, 0.f);

    for (int base = 0; base < deg; base += 32) {
        int m = deg - base; if (m > 32) m = 32;
        int myS = (lane < m) ? bk[base + lane] : 0;
        int i = 0;
        for (; i + 4 <= m; i += 4) {
            int s0 = __shfl_sync(0xffffffff, myS, i);
            int s1 = __shfl_sync(0xffffffff, myS, i + 1);
            int s2 = __shfl_sync(0xffffffff, myS, i + 2);
            int s3 = __shfl_sync(0xffffffff, myS, i + 3);
            float4 h0 = H4[(size_t)s0 * 32 + lane];
            float4 h1 = H4[(size_t)s1 * 32 + lane];
            float4 h2 = H4[(size_t)s2 * 32 + lane];
            float4 h3 = H4[(size_t)s3 * 32 + lane];
            acc0.x += h0.x; acc0.y += h0.y; acc0.z += h0.z; acc0.w += h0.w;
            acc1.x += h1.x; acc1.y += h1.y; acc1.z += h1.z; acc1.w += h1.w;
            acc2.x += h2.x; acc2.y += h2.y; acc2.z += h2.z; acc2.w += h2.w;
            acc3.x += h3.x; acc3.y += h3.y; acc3.z += h3.z; acc3.w += h3.w;
        }
        for (; i < m; i++) {
            int s0 = __shfl_sync(0xffffffff, myS, i);
            float4 h0 = H4[(size_t)s0 * 32 + lane];
            acc0.x += h0.x; acc0.y += h0.y; acc0.z += h0.z; acc0.w += h0.w;
        }
    }

    float dv = rsqrtf(1.0f + (float)rawdeg);
    const float4 bb = ((const float4*)bias)[lane];
    float4 s;
    s.x = fmaxf(fmaf((acc0.x + acc1.x) + (acc2.x + acc3.x), dv, bb.x), 0.f);
    s.y = fmaxf(fmaf((acc0.y + acc1.y) + (acc2.y + acc3.y), dv, bb.y), 0.f);
    s.z = fmaxf(fmaf((acc0.z + acc1.z) + (acc2.z + acc3.z), dv, bb.z), 0.f);
    s.w = fmaxf(fmaf((acc0.w + acc1.w) + (acc2.w + acc3.w), dv, bb.w), 0.f);

    int k0 = lane * 4;
#pragma unroll
    for (int o = 0; o < OUTD; o++) {
        float p = s.x * Wrs[(k0 + 0) * OUTD + o]
                + s.y * Wrs[(k0 + 1) * OUTD + o]
                + s.z * Wrs[(k0 + 2) * OUTD + o]
                + s.w * Wrs[(k0 + 3) * OUTD + o];
#pragma unroll
        for (int off = 16; off > 0; off >>= 1)
            p += __shfl_xor_sync(0xffffffff, p, off);
        if (lane == 0) out[warp * OUTD + o] = p + brs[o];
    }
}

// ---------------------------------------------------------------------------
// Launch
// ---------------------------------------------------------------------------
extern "C" void kernel_launch(void* const* d_in, const int* in_sizes, int n_in,
                              void* d_out, int out_size) {
    const float* x    = (const float*)d_in[0];
    const int*   ei   = (const int*)d_in[1];
    const int*   tgt  = (const int*)d_in[2];
    const float* W1   = (const float*)d_in[3];
    const float* b1   = (const float*)d_in[4];
    const float* W2   = (const float*)d_in[5];
    const float* b2   = (const float*)d_in[6];
    const float* W3   = (const float*)d_in[7];
    const float* b3   = (const float*)d_in[8];
    const float* Wr   = (const float*)d_in[9];
    const float* br   = (const float*)d_in[10];
    float* out = (float*)d_out;

    const int n    = in_sizes[0] / DIM;
    const int E    = in_sizes[1] / 2;
    const int ntgt = in_sizes[2];
    const int* src = ei;
    const int* dst = ei + E;

    float *H, *A, *B, *Wt;
    int *cnt, *bucket;
    cudaGetSymbolAddress((void**)&H,      g_H);
    cudaGetSymbolAddress((void**)&A,      g_A);
    cudaGetSymbolAddress((void**)&B,      g_B);
    cudaGetSymbolAddress((void**)&Wt,     g_Wt);
    cudaGetSymbolAddress((void**)&cnt,    g_cnt);
    cudaGetSymbolAddress((void**)&bucket, g_bucket);

    cudaFuncSetAttribute(k_gemm_tc<true>, cudaFuncAttributeMaxDynamicSharedMemorySize,
                         GEMM_SMEM_BYTES);
    cudaFuncSetAttribute(k_gemm_tc<false>, cudaFuncAttributeMaxDynamicSharedMemorySize,
                         GEMM_SMEM_BYTES);

    const int TPB = 256;
    const int nBlk    = (n + TPB - 1) / TPB;
    const int eBlk    = (E + TPB - 1) / TPB;
    const int gemmBlk = (n + 127) / 128;
    const int pullBlk = ((n * 32) + TPB - 1) / TPB;
    const int prBlk   = ((ntgt * 32) + TPB - 1) / TPB;

    // 1: transpose+round weights, zero counts (fused); 2: buckets
    k_pre<<<48 + nBlk, TPB>>>(W1, W2, W3, Wt, cnt, n);
    k_fill<<<eBlk, TPB>>>(src, dst, cnt, bucket, E);

    // Conv 1: x -> A
    k_gemm_tc<true><<<gemmBlk, 256, GEMM_SMEM_BYTES>>>(x, Wt, cnt, H, n);
    k_pull<<<pullBlk, TPB>>>(bucket, cnt, H, b1, A, n);

    // Conv 2: A -> B
    k_gemm_tc<false><<<gemmBlk, 256, GEMM_SMEM_BYTES>>>(A, Wt + DIM * DIM, cnt, H, n);
    k_pull<<<pullBlk, TPB>>>(bucket, cnt, H, b2, B, n);

    // Conv 3 GEMM: B -> H, then fused target-only pull + regressor
    k_gemm_tc<false><<<gemmBlk, 256, GEMM_SMEM_BYTES>>>(B, Wt + 2 * DIM * DIM, cnt, H, n);
    k_pull_regress<<<prBlk, TPB>>>(bucket, cnt, H, b3, tgt, Wr, br, out, ntgt);
}

// round 16
// speedup vs baseline: 1.5128x; 1.0393x over previous
#include <cuda_runtime.h>
#include <cuda_bf16.h>
#include <cuda_fp16.h>
#include <cstdint>

// Problem constants (fixed by the dataset)
#define N_NODES 50000
#define N_EDGES 800000
#define DIM     128
#define OUTD    12
#define CAP     128          // per-node in-edge bucket capacity (Poisson(16) degree)

// ---------------------------------------------------------------------------
// Device scratch (no allocations allowed)
// ---------------------------------------------------------------------------
__device__ __half g_H[N_NODES * DIM];       // GEMM output (dinv-scaled), fp16
__device__ float  g_A[N_NODES * DIM];       // ping (tf32-rounded activations)
__device__ float  g_B[N_NODES * DIM];       // pong
__device__ float  g_Wt[3 * DIM * DIM];      // transposed + tf32-rounded weights
__device__ int    g_cnt[N_NODES];
__device__ int    g_bucket[N_NODES * CAP];  // in-edge src lists per dst

__device__ __forceinline__ uint32_t f2tf32(float f) {
    uint32_t u;
    asm("cvt.rna.tf32.f32 %0, %1;" : "=r"(u) : "f"(f));
    return u;
}

__device__ __forceinline__ uint32_t smem_u32(const void* p) {
    uint32_t a;
    asm("{ .reg .u64 t; cvta.to.shared.u64 t, %1; cvt.u32.u64 %0, t; }" : "=r"(a) : "l"(p));
    return a;
}

__device__ __forceinline__ void mma_tf32(float* d, const uint32_t* a,
                                         uint32_t b0, uint32_t b1) {
    asm volatile(
        "mma.sync.aligned.m16n8k8.row.col.f32.tf32.tf32.f32 "
        "{%0,%1,%2,%3}, {%4,%5,%6,%7}, {%8,%9}, {%0,%1,%2,%3};"
        : "+f"(d[0]), "+f"(d[1]), "+f"(d[2]), "+f"(d[3])
        : "r"(a[0]), "r"(a[1]), "r"(a[2]), "r"(a[3]), "r"(b0), "r"(b1));
}

// ---------------------------------------------------------------------------
// Fused precompute: blocks 0..47 transpose+round weights, rest zero cnt.
// ---------------------------------------------------------------------------
__global__ void k_pre(const float* __restrict__ W1, const float* __restrict__ W2,
                      const float* __restrict__ W3, float* __restrict__ Wt,
                      int* __restrict__ cnt, int n) {
    int b = blockIdx.x;
    int t = threadIdx.x;
    if (b < 48) {
        __shared__ float tile[32][33];
        int bz = b >> 4, rem = b & 15, bx = rem & 3, by = rem >> 2;
        const float* W = (bz == 0) ? W1 : (bz == 1) ? W2 : W3;
        float* dst = Wt + (size_t)bz * DIM * DIM;
        int tx = t & 31, ty = t >> 5;
        int x = bx * 32 + tx, y = by * 32 + ty;
#pragma unroll
        for (int j = 0; j < 32; j += 8)
            tile[ty + j][tx] = W[(y + j) * DIM + x];
        __syncthreads();
        x = by * 32 + tx; y = bx * 32 + ty;
#pragma unroll
        for (int j = 0; j < 32; j += 8)
            dst[(y + j) * DIM + x] = __uint_as_float(f2tf32(tile[tx][ty + j]));
    } else {
        int i = (b - 48) * 256 + t;
        if (i < n) cnt[i] = 0;
    }
}

__global__ void k_fill(const int* __restrict__ src, const int* __restrict__ dst,
                       int* cnt, int* bucket, int E) {
    int e = blockIdx.x * blockDim.x + threadIdx.x;
    if (e >= E) return;
    int d = dst[e];
    int pos = atomicAdd(&cnt[d], 1);
    if (pos < CAP) bucket[(size_t)d * CAP + pos] = src[e];
}

// ---------------------------------------------------------------------------
// tf32 tensor-core GEMM (R9 shape): 128x128 tile, 256 threads, B-resident.
// H'[r] = half( rsqrt(1+cnt[r]) * (X[r] @ W) )   -- fp16 output.
// Epilogue repacks half2 via smem (stride-65 u32) into coalesced 16B stores.
// smem 110592 B, 2 CTAs/SM.  CVTA=true: RNA-round A frags (layer 1 only).
// ---------------------------------------------------------------------------
#define CLD 36
#define CHUNK (DIM * CLD)                 // 4608 u32
#define GEMM_SMEM_BYTES (6 * CHUNK * 4)   // 110592 B
#define ELD 65                            // epilogue smem row stride (u32)

template <bool CVTA>
__global__ void __launch_bounds__(256, 2) k_gemm_tc(
    const float* __restrict__ X, const float* __restrict__ Bt,
    const int* __restrict__ cnt, __half* __restrict__ H, int n) {
    extern __shared__ uint32_t smem[];
    const int tid  = threadIdx.x;
    const int row0 = blockIdx.x * 128;
    const uint32_t sbase = smem_u32(smem);

    auto stage_x = [&](int c) {
        const uint32_t xb = sbase + (uint32_t)(c & 1) * (CHUNK * 4);
        const float4* X4 = (const float4*)X;
#pragma unroll
        for (int i = 0; i < 4; i++) {
            int idx = tid + i * 256;
            int r = idx >> 3, c4 = idx & 7;
            uint32_t off = (uint32_t)(r * CLD + c4 * 4) * 4;
            const float4* xsrc = X4 + ((size_t)(row0 + r) * 32 + c * 8 + c4);
            int vs = (row0 + r < n) ? 16 : 0;
            asm volatile("cp.async.cg.shared.global [%0], [%1], 16, %2;"
                         :: "r"(xb + off), "l"(xsrc), "r"(vs));
        }
    };
    auto stage_b = [&](int c) {
        const uint32_t bb = sbase + (uint32_t)(2 + c) * (CHUNK * 4);
        const float4* B4 = (const float4*)Bt;
#pragma unroll
        for (int i = 0; i < 4; i++) {
            int idx = tid + i * 256;
            int r = idx >> 3, c4 = idx & 7;
            uint32_t off = (uint32_t)(r * CLD + c4 * 4) * 4;
            const float4* bsrc = B4 + ((size_t)r * 32 + c * 8 + c4);
            asm volatile("cp.async.cg.shared.global [%0], [%1], 16;"
                         :: "r"(bb + off), "l"(bsrc));
        }
    };

    stage_b(0); stage_b(1); stage_b(2); stage_b(3);
    stage_x(0);
    asm volatile("cp.async.commit_group;" ::: "memory");
    stage_x(1);
    asm volatile("cp.async.commit_group;" ::: "memory");

    const int warp = tid >> 5;
    const int lane = tid & 31;
    const int wm   = warp & 3;
    const int wn   = warp >> 2;
    const int g    = lane >> 2;
    const int tg   = lane & 3;

    float acc[2][8][4];
#pragma unroll
    for (int mt = 0; mt < 2; mt++)
#pragma unroll
        for (int nt = 0; nt < 8; nt++)
#pragma unroll
            for (int q = 0; q < 4; q++) acc[mt][nt][q] = 0.f;

#pragma unroll
    for (int c = 0; c < 4; c++) {
        if (c < 3) asm volatile("cp.async.wait_group 1;" ::: "memory");
        else       asm volatile("cp.async.wait_group 0;" ::: "memory");
        __syncthreads();

        const uint32_t* Xs = smem + (c & 1) * CHUNK;
        const uint32_t* Ws = smem + (2 + c) * CHUNK;

#pragma unroll
        for (int ks = 0; ks < 4; ks++) {
            const int k0 = ks * 8;
            uint32_t a[2][4];
#pragma unroll
            for (int mt = 0; mt < 2; mt++) {
                int r0 = wm * 32 + mt * 16;
                a[mt][0] = Xs[(r0 + g) * CLD + k0 + tg];
                a[mt][1] = Xs[(r0 + 8 + g) * CLD + k0 + tg];
                a[mt][2] = Xs[(r0 + g) * CLD + k0 + tg + 4];
                a[mt][3] = Xs[(r0 + 8 + g) * CLD + k0 + tg + 4];
                if (CVTA) {
#pragma unroll
                    for (int q = 0; q < 4; q++)
                        a[mt][q] = f2tf32(__uint_as_float(a[mt][q]));
                }
            }
#pragma unroll
            for (int nt = 0; nt < 8; nt++) {
                int c0 = wn * 64 + nt * 8;
                uint32_t b0 = Ws[(c0 + g) * CLD + k0 + tg];
                uint32_t b1 = Ws[(c0 + g) * CLD + k0 + tg + 4];
                mma_tf32(acc[0][nt], a[0], b0, b1);
                mma_tf32(acc[1][nt], a[1], b0, b1);
            }
        }
        __syncthreads();
        if (c + 2 < 4) {
            stage_x(c + 2);
            asm volatile("cp.async.commit_group;" ::: "memory");
        }
    }

    // Epilogue: dinv scale, half2 pack into smem [128][ELD], coalesced STG.128.
    __syncthreads();   // all smem chunk reads complete; smem reusable
#pragma unroll
    for (int mt = 0; mt < 2; mt++) {
        int rl0 = wm * 32 + mt * 16 + g;
        int rl1 = rl0 + 8;
        int gr0 = row0 + rl0, gr1 = row0 + rl1;
        float dv0 = (gr0 < n) ? rsqrtf(1.0f + (float)cnt[gr0]) : 0.f;
        float dv1 = (gr1 < n) ? rsqrtf(1.0f + (float)cnt[gr1]) : 0.f;
#pragma unroll
        for (int nt = 0; nt < 8; nt++) {
            int cu = wn * 32 + nt * 4 + tg;   // u32 (half2) column index
            __half2 h0 = __floats2half2_rn(acc[mt][nt][0] * dv0, acc[mt][nt][1] * dv0);
            __half2 h1 = __floats2half2_rn(acc[mt][nt][2] * dv1, acc[mt][nt][3] * dv1);
            smem[rl0 * ELD + cu] = *(uint32_t*)&h0;
            smem[rl1 * ELD + cu] = *(uint32_t*)&h1;
        }
    }
    __syncthreads();

    uint4* H16 = (uint4*)H;   // 16 uint4 per row (256 B)
#pragma unroll
    for (int k = 0; k < 8; k++) {
        int idx = tid + k * 256;
        int row = idx >> 4, q = idx & 15;
        int gr = row0 + row;
        if (gr < n) {
            uint4 v;
            v.x = smem[row * ELD + q * 4 + 0];
            v.y = smem[row * ELD + q * 4 + 1];
            v.z = smem[row * ELD + q * 4 + 2];
            v.w = smem[row * ELD + q * 4 + 3];
            H16[(size_t)gr * 16 + q] = v;
        }
    }
}

// ---------------------------------------------------------------------------
// Pull aggregation (layers 1-2): one warp per destination node, fp16 gather.
// OUT[v] = rna_tf32(relu(bias + dinv[v] * (H'[v] + sum_{s in in(v)} H'[s])))
// ---------------------------------------------------------------------------
__global__ void k_pull(const int* __restrict__ bucket, const int* __restrict__ cnt,
                       const __half* __restrict__ H,
                       const float* __restrict__ bias, float* __restrict__ OUT, int n) {
    int warp = (blockIdx.x * blockDim.x + threadIdx.x) >> 5;
    int lane = threadIdx.x & 31;
    if (warp >= n) return;
    const int v = warp;
    int rawdeg = cnt[v];
    int deg = rawdeg > CAP ? CAP : rawdeg;
    const int* bk = bucket + (size_t)v * CAP;
    const uint2* H2 = (const uint2*)H;   // 4 halfs (8B) per lane, 32 lanes/row

    float4 acc0, acc1, acc2, acc3;
    {   // self-loop term
        uint2 raw = H2[(size_t)v * 32 + lane];
        float2 lo = __half22float2(*(__half2*)&raw.x);
        float2 hi = __half22float2(*(__half2*)&raw.y);
        acc0 = make_float4(lo.x, lo.y, hi.x, hi.y);
        acc1 = make_float4(0.f, 0.f, 0.f, 0.f);
        acc2 = make_float4(0.f, 0.f, 0.f, 0.f);
        acc3 = make_float4(0.f, 0.f, 0.f, 0.f);
    }

    for (int base = 0; base < deg; base += 32) {
        int m = deg - base; if (m > 32) m = 32;
        int myS = (lane < m) ? bk[base + lane] : 0;
        int i = 0;
        for (; i + 4 <= m; i += 4) {
            int s0 = __shfl_sync(0xffffffff, myS, i);
            int s1 = __shfl_sync(0xffffffff, myS, i + 1);
            int s2 = __shfl_sync(0xffffffff, myS, i + 2);
            int s3 = __shfl_sync(0xffffffff, myS, i + 3);
            uint2 r0 = H2[(size_t)s0 * 32 + lane];
            uint2 r1 = H2[(size_t)s1 * 32 + lane];
            uint2 r2 = H2[(size_t)s2 * 32 + lane];
            uint2 r3 = H2[(size_t)s3 * 32 + lane];
            float2 a0 = __half22float2(*(__half2*)&r0.x), b0 = __half22float2(*(__half2*)&r0.y);
            float2 a1 = __half22float2(*(__half2*)&r1.x), b1 = __half22float2(*(__half2*)&r1.y);
            float2 a2 = __half22float2(*(__half2*)&r2.x), b2 = __half22float2(*(__half2*)&r2.y);
            float2 a3 = __half22float2(*(__half2*)&r3.x), b3 = __half22float2(*(__half2*)&r3.y);
            acc0.x += a0.x; acc0.y += a0.y; acc0.z += b0.x; acc0.w += b0.y;
            acc1.x += a1.x; acc1.y += a1.y; acc1.z += b1.x; acc1.w += b1.y;
            acc2.x += a2.x; acc2.y += a2.y; acc2.z += b2.x; acc2.w += b2.y;
            acc3.x += a3.x; acc3.y += a3.y; acc3.z += b3.x; acc3.w += b3.y;
        }
        for (; i < m; i++) {
            int s0 = __shfl_sync(0xffffffff, myS, i);
            uint2 r0 = H2[(size_t)s0 * 32 + lane];
            float2 a0 = __half22float2(*(__half2*)&r0.x), b0 = __half22float2(*(__half2*)&r0.y);
            acc0.x += a0.x; acc0.y += a0.y; acc0.z += b0.x; acc0.w += b0.y;
        }
    }

    float dv = rsqrtf(1.0f + (float)rawdeg);
    const float4 bb = ((const float4*)bias)[lane];
    float sx = (acc0.x + acc1.x) + (acc2.x + acc3.x);
    float sy = (acc0.y + acc1.y) + (acc2.y + acc3.y);
    float sz = (acc0.z + acc1.z) + (acc2.z + acc3.z);
    float sw = (acc0.w + acc1.w) + (acc2.w + acc3.w);
    float4 o;
    o.x = __uint_as_float(f2tf32(fmaxf(fmaf(sx, dv, bb.x), 0.f)));
    o.y = __uint_as_float(f2tf32(fmaxf(fmaf(sy, dv, bb.y), 0.f)));
    o.z = __uint_as_float(f2tf32(fmaxf(fmaf(sz, dv, bb.z), 0.f)));
    o.w = __uint_as_float(f2tf32(fmaxf(fmaf(sw, dv, bb.w), 0.f)));
    ((float4*)OUT)[(size_t)v * 32 + lane] = o;
}

// ---------------------------------------------------------------------------
// FUSED final pull + regressor on the 8192 target nodes (fp16 gather).
// ---------------------------------------------------------------------------
__global__ void k_pull_regress(
    const int* __restrict__ bucket, const int* __restrict__ cnt,
    const __half* __restrict__ H, const float* __restrict__ bias,
    const int* __restrict__ tgt, const float* __restrict__ Wr,
    const float* __restrict__ br, float* __restrict__ out, int ntgt) {
    __shared__ float Wrs[DIM * OUTD];
    __shared__ float brs[OUTD];
    int tid = threadIdx.x;
    for (int i = tid; i < DIM * OUTD; i += blockDim.x) Wrs[i] = Wr[i];
    if (tid < OUTD) brs[tid] = br[tid];
    __syncthreads();

    int warp = (blockIdx.x * blockDim.x + tid) >> 5;
    int lane = tid & 31;
    if (warp >= ntgt) return;
    const int v = tgt[warp];
    int rawdeg = cnt[v];
    int deg = rawdeg > CAP ? CAP : rawdeg;
    const int* bk = bucket + (size_t)v * CAP;
    const uint2* H2 = (const uint2*)H;

    float4 acc0, acc1, acc2, acc3;
    {
        uint2 raw = H2[(size_t)v * 32 + lane];
        float2 lo = __half22float2(*(__half2*)&raw.x);
        float2 hi = __half22float2(*(__half2*)&raw.y);
        acc0 = make_float4(lo.x, lo.y, hi.x, hi.y);
        acc1 = make_float4(0.f, 0.f, 0.f, 0.f);
        acc2 = make_float4(0.f, 0.f, 0.f, 0.f);
        acc3 = make_float4(0.f, 0.f, 0.f, 0.f);
    }

    for (int base = 0; base < deg; base += 32) {
        int m = deg - base; if (m > 32) m = 32;
        int myS = (lane < m) ? bk[base + lane] : 0;
        int i = 0;
        for (; i + 4 <= m; i += 4) {
            int s0 = __shfl_sync(0xffffffff, myS, i);
            int s1 = __shfl_sync(0xffffffff, myS, i + 1);
            int s2 = __shfl_sync(0xffffffff, myS, i + 2);
            int s3 = __shfl_sync(0xffffffff, myS, i + 3);
            uint2 r0 = H2[(size_t)s0 * 32 + lane];
            uint2 r1 = H2[(size_t)s1 * 32 + lane];
            uint2 r2 = H2[(size_t)s2 * 32 + lane];
            uint2 r3 = H2[(size_t)s3 * 32 + lane];
            float2 a0 = __half22float2(*(__half2*)&r0.x), b0 = __half22float2(*(__half2*)&r0.y);
            float2 a1 = __half22float2(*(__half2*)&r1.x), b1 = __half22float2(*(__half2*)&r1.y);
            float2 a2 = __half22float2(*(__half2*)&r2.x), b2 = __half22float2(*(__half2*)&r2.y);
            float2 a3 = __half22float2(*(__half2*)&r3.x), b3 = __half22float2(*(__half2*)&r3.y);
            acc0.x += a0.x; acc0.y += a0.y; acc0.z += b0.x; acc0.w += b0.y;
            acc1.x += a1.x; acc1.y += a1.y; acc1.z += b1.x; acc1.w += b1.y;
            acc2.x += a2.x; acc2.y += a2.y; acc2.z += b2.x; acc2.w += b2.y;
            acc3.x += a3.x; acc3.y += a3.y; acc3.z += b3.x; acc3.w += b3.y;
        }
        for (; i < m; i++) {
            int s0 = __shfl_sync(0xffffffff, myS, i);
            uint2 r0 = H2[(size_t)s0 * 32 + lane];
            float2 a0 = __half22float2(*(__half2*)&r0.x), b0 = __half22float2(*(__half2*)&r0.y);
            acc0.x += a0.x; acc0.y += a0.y; acc0.z += b0.x; acc0.w += b0.y;
        }
    }

    float dv = rsqrtf(1.0f + (float)rawdeg);
    const float4 bb = ((const float4*)bias)[lane];
    float4 s;
    s.x = fmaxf(fmaf((acc0.x + acc1.x) + (acc2.x + acc3.x), dv, bb.x), 0.f);
    s.y = fmaxf(fmaf((acc0.y + acc1.y) + (acc2.y + acc3.y), dv, bb.y), 0.f);
    s.z = fmaxf(fmaf((acc0.z + acc1.z) + (acc2.z + acc3.z), dv, bb.z), 0.f);
    s.w = fmaxf(fmaf((acc0.w + acc1.w) + (acc2.w + acc3.w), dv, bb.w), 0.f);

    int k0 = lane * 4;
#pragma unroll
    for (int o = 0; o < OUTD; o++) {
        float p = s.x * Wrs[(k0 + 0) * OUTD + o]
                + s.y * Wrs[(k0 + 1) * OUTD + o]
                + s.z * Wrs[(k0 + 2) * OUTD + o]
                + s.w * Wrs[(k0 + 3) * OUTD + o];
#pragma unroll
        for (int off = 16; off > 0; off >>= 1)
            p += __shfl_xor_sync(0xffffffff, p, off);
        if (lane == 0) out[warp * OUTD + o] = p + brs[o];
    }
}

// ---------------------------------------------------------------------------
// Launch
// ---------------------------------------------------------------------------
extern "C" void kernel_launch(void* const* d_in, const int* in_sizes, int n_in,
                              void* d_out, int out_size) {
    const float* x    = (const float*)d_in[0];
    const int*   ei   = (const int*)d_in[1];
    const int*   tgt  = (const int*)d_in[2];
    const float* W1   = (const float*)d_in[3];
    const float* b1   = (const float*)d_in[4];
    const float* W2   = (const float*)d_in[5];
    const float* b2   = (const float*)d_in[6];
    const float* W3   = (const float*)d_in[7];
    const float* b3   = (const float*)d_in[8];
    const float* Wr   = (const float*)d_in[9];
    const float* br   = (const float*)d_in[10];
    float* out = (float*)d_out;

    const int n    = in_sizes[0] / DIM;
    const int E    = in_sizes[1] / 2;
    const int ntgt = in_sizes[2];
    const int* src = ei;
    const int* dst = ei + E;

    __half* H;
    float *A, *B, *Wt;
    int *cnt, *bucket;
    cudaGetSymbolAddress((void**)&H,      g_H);
    cudaGetSymbolAddress((void**)&A,      g_A);
    cudaGetSymbolAddress((void**)&B,      g_B);
    cudaGetSymbolAddress((void**)&Wt,     g_Wt);
    cudaGetSymbolAddress((void**)&cnt,    g_cnt);
    cudaGetSymbolAddress((void**)&bucket, g_bucket);

    cudaFuncSetAttribute(k_gemm_tc<true>, cudaFuncAttributeMaxDynamicSharedMemorySize,
                         GEMM_SMEM_BYTES);
    cudaFuncSetAttribute(k_gemm_tc<false>, cudaFuncAttributeMaxDynamicSharedMemorySize,
                         GEMM_SMEM_BYTES);

    const int TPB = 256;
    const int nBlk    = (n + TPB - 1) / TPB;
    const int eBlk    = (E + TPB - 1) / TPB;
    const int gemmBlk = (n + 127) / 128;
    const int pullBlk = ((n * 32) + TPB - 1) / TPB;
    const int prBlk   = ((ntgt * 32) + TPB - 1) / TPB;

    // 1: transpose+round weights, zero counts (fused); 2: buckets
    k_pre<<<48 + nBlk, TPB>>>(W1, W2, W3, Wt, cnt, n);
    k_fill<<<eBlk, TPB>>>(src, dst, cnt, bucket, E);

    // Conv 1: x -> A
    k_gemm_tc<true><<<gemmBlk, 256, GEMM_SMEM_BYTES>>>(x, Wt, cnt, H, n);
    k_pull<<<pullBlk, TPB>>>(bucket, cnt, H, b1, A, n);

    // Conv 2: A -> B
    k_gemm_tc<false><<<gemmBlk, 256, GEMM_SMEM_BYTES>>>(A, Wt + DIM * DIM, cnt, H, n);
    k_pull<<<pullBlk, TPB>>>(bucket, cnt, H, b2, B, n);

    // Conv 3 GEMM: B -> H, then fused target-only pull + regressor
    k_gemm_tc<false><<<gemmBlk, 256, GEMM_SMEM_BYTES>>>(B, Wt + 2 * DIM * DIM, cnt, H, n);
    k_pull_regress<<<prBlk, TPB>>>(bucket, cnt, H, b3, tgt, Wr, br, out, ntgt);
}

// round 17
// speedup vs baseline: 1.5951x; 1.0544x over previous
#include <cuda_runtime.h>
#include <cuda_bf16.h>
#include <cuda_fp16.h>
#include <cstdint>

// Problem constants (fixed by the dataset)
#define N_NODES 50000
#define N_EDGES 800000
#define DIM     128
#define OUTD    12
#define CAP     128          // per-node in-edge bucket capacity (Poisson(16) degree)

// ---------------------------------------------------------------------------
// Device scratch (no allocations allowed)
// ---------------------------------------------------------------------------
__device__ __half g_H[N_NODES * DIM];       // GEMM output (dinv-scaled), fp16
__device__ float  g_A[N_NODES * DIM];       // ping (tf32-rounded activations)
__device__ float  g_B[N_NODES * DIM];       // pong
__device__ float  g_Wt[3 * DIM * DIM];      // transposed + tf32-rounded weights
__device__ int    g_cnt[N_NODES];
__device__ int    g_bucket[N_NODES * CAP];  // in-edge src lists per dst

__device__ __forceinline__ uint32_t f2tf32(float f) {
    uint32_t u;
    asm("cvt.rna.tf32.f32 %0, %1;" : "=r"(u) : "f"(f));
    return u;
}

__device__ __forceinline__ uint32_t smem_u32(const void* p) {
    uint32_t a;
    asm("{ .reg .u64 t; cvta.to.shared.u64 t, %1; cvt.u32.u64 %0, t; }" : "=r"(a) : "l"(p));
    return a;
}

__device__ __forceinline__ void mma_tf32(float* d, const uint32_t* a,
                                         uint32_t b0, uint32_t b1) {
    asm volatile(
        "mma.sync.aligned.m16n8k8.row.col.f32.tf32.tf32.f32 "
        "{%0,%1,%2,%3}, {%4,%5,%6,%7}, {%8,%9}, {%0,%1,%2,%3};"
        : "+f"(d[0]), "+f"(d[1]), "+f"(d[2]), "+f"(d[3])
        : "r"(a[0]), "r"(a[1]), "r"(a[2]), "r"(a[3]), "r"(b0), "r"(b1));
}

// Warp-level gather-accumulate over one 32-edge block with 8-deep MLP.
// Returns partial sums in acc[4] (float4 each).
__device__ __forceinline__ void gather_block(
    const uint2* __restrict__ H2, int myS, int m, int lane, float4* acc) {
    int i = 0;
    for (; i + 8 <= m; i += 8) {
        int s[8];
#pragma unroll
        for (int j = 0; j < 8; j++) s[j] = __shfl_sync(0xffffffff, myS, i + j);
        uint2 r[8];
#pragma unroll
        for (int j = 0; j < 8; j++) r[j] = H2[(size_t)s[j] * 32 + lane];
#pragma unroll
        for (int j = 0; j < 8; j++) {
            float2 a = __half22float2(*(__half2*)&r[j].x);
            float2 b = __half22float2(*(__half2*)&r[j].y);
            float4& A = acc[j & 3];
            A.x += a.x; A.y += a.y; A.z += b.x; A.w += b.y;
        }
    }
    if (i + 4 <= m) {
        int s[4];
#pragma unroll
        for (int j = 0; j < 4; j++) s[j] = __shfl_sync(0xffffffff, myS, i + j);
        uint2 r[4];
#pragma unroll
        for (int j = 0; j < 4; j++) r[j] = H2[(size_t)s[j] * 32 + lane];
#pragma unroll
        for (int j = 0; j < 4; j++) {
            float2 a = __half22float2(*(__half2*)&r[j].x);
            float2 b = __half22float2(*(__half2*)&r[j].y);
            float4& A = acc[j];
            A.x += a.x; A.y += a.y; A.z += b.x; A.w += b.y;
        }
        i += 4;
    }
    for (; i < m; i++) {
        int s0 = __shfl_sync(0xffffffff, myS, i);
        uint2 r0 = H2[(size_t)s0 * 32 + lane];
        float2 a = __half22float2(*(__half2*)&r0.x);
        float2 b = __half22float2(*(__half2*)&r0.y);
        acc[0].x += a.x; acc[0].y += a.y; acc[0].z += b.x; acc[0].w += b.y;
    }
}

// ---------------------------------------------------------------------------
// Fused precompute: blocks 0..47 transpose+round weights, rest zero cnt.
// ---------------------------------------------------------------------------
__global__ void k_pre(const float* __restrict__ W1, const float* __restrict__ W2,
                      const float* __restrict__ W3, float* __restrict__ Wt,
                      int* __restrict__ cnt, int n) {
    int b = blockIdx.x;
    int t = threadIdx.x;
    if (b < 48) {
        __shared__ float tile[32][33];
        int bz = b >> 4, rem = b & 15, bx = rem & 3, by = rem >> 2;
        const float* W = (bz == 0) ? W1 : (bz == 1) ? W2 : W3;
        float* dst = Wt + (size_t)bz * DIM * DIM;
        int tx = t & 31, ty = t >> 5;
        int x = bx * 32 + tx, y = by * 32 + ty;
#pragma unroll
        for (int j = 0; j < 32; j += 8)
            tile[ty + j][tx] = W[(y + j) * DIM + x];
        __syncthreads();
        x = by * 32 + tx; y = bx * 32 + ty;
#pragma unroll
        for (int j = 0; j < 32; j += 8)
            dst[(y + j) * DIM + x] = __uint_as_float(f2tf32(tile[tx][ty + j]));
    } else {
        int i = (b - 48) * 256 + t;
        if (i < n) cnt[i] = 0;
    }
}

__global__ void k_fill(const int* __restrict__ src, const int* __restrict__ dst,
                       int* cnt, int* bucket, int E) {
    int e = blockIdx.x * blockDim.x + threadIdx.x;
    if (e >= E) return;
    int d = dst[e];
    int pos = atomicAdd(&cnt[d], 1);
    if (pos < CAP) bucket[(size_t)d * CAP + pos] = src[e];
}

// ---------------------------------------------------------------------------
// tf32 tensor-core GEMM (R9 shape): 128x128 tile, 256 threads, B-resident.
// H'[r] = half( rsqrt(1+cnt[r]) * (X[r] @ W) )   -- fp16 output.
// Epilogue repacks half2 via smem (stride-65 u32) into coalesced 16B stores.
// smem 110592 B, 2 CTAs/SM.  CVTA=true: RNA-round A frags (layer 1 only).
// ---------------------------------------------------------------------------
#define CLD 36
#define CHUNK (DIM * CLD)                 // 4608 u32
#define GEMM_SMEM_BYTES (6 * CHUNK * 4)   // 110592 B
#define ELD 65                            // epilogue smem row stride (u32)

template <bool CVTA>
__global__ void __launch_bounds__(256, 2) k_gemm_tc(
    const float* __restrict__ X, const float* __restrict__ Bt,
    const int* __restrict__ cnt, __half* __restrict__ H, int n) {
    extern __shared__ uint32_t smem[];
    const int tid  = threadIdx.x;
    const int row0 = blockIdx.x * 128;
    const uint32_t sbase = smem_u32(smem);

    auto stage_x = [&](int c) {
        const uint32_t xb = sbase + (uint32_t)(c & 1) * (CHUNK * 4);
        const float4* X4 = (const float4*)X;
#pragma unroll
        for (int i = 0; i < 4; i++) {
            int idx = tid + i * 256;
            int r = idx >> 3, c4 = idx & 7;
            uint32_t off = (uint32_t)(r * CLD + c4 * 4) * 4;
            const float4* xsrc = X4 + ((size_t)(row0 + r) * 32 + c * 8 + c4);
            int vs = (row0 + r < n) ? 16 : 0;
            asm volatile("cp.async.cg.shared.global [%0], [%1], 16, %2;"
                         :: "r"(xb + off), "l"(xsrc), "r"(vs));
        }
    };
    auto stage_b = [&](int c) {
        const uint32_t bb = sbase + (uint32_t)(2 + c) * (CHUNK * 4);
        const float4* B4 = (const float4*)Bt;
#pragma unroll
        for (int i = 0; i < 4; i++) {
            int idx = tid + i * 256;
            int r = idx >> 3, c4 = idx & 7;
            uint32_t off = (uint32_t)(r * CLD + c4 * 4) * 4;
            const float4* bsrc = B4 + ((size_t)r * 32 + c * 8 + c4);
            asm volatile("cp.async.cg.shared.global [%0], [%1], 16;"
                         :: "r"(bb + off), "l"(bsrc));
        }
    };

    stage_b(0); stage_b(1); stage_b(2); stage_b(3);
    stage_x(0);
    asm volatile("cp.async.commit_group;" ::: "memory");
    stage_x(1);
    asm volatile("cp.async.commit_group;" ::: "memory");

    const int warp = tid >> 5;
    const int lane = tid & 31;
    const int wm   = warp & 3;
    const int wn   = warp >> 2;
    const int g    = lane >> 2;
    const int tg   = lane & 3;

    float acc[2][8][4];
#pragma unroll
    for (int mt = 0; mt < 2; mt++)
#pragma unroll
        for (int nt = 0; nt < 8; nt++)
#pragma unroll
            for (int q = 0; q < 4; q++) acc[mt][nt][q] = 0.f;

#pragma unroll
    for (int c = 0; c < 4; c++) {
        if (c < 3) asm volatile("cp.async.wait_group 1;" ::: "memory");
        else       asm volatile("cp.async.wait_group 0;" ::: "memory");
        __syncthreads();

        const uint32_t* Xs = smem + (c & 1) * CHUNK;
        const uint32_t* Ws = smem + (2 + c) * CHUNK;

#pragma unroll
        for (int ks = 0; ks < 4; ks++) {
            const int k0 = ks * 8;
            uint32_t a[2][4];
#pragma unroll
            for (int mt = 0; mt < 2; mt++) {
                int r0 = wm * 32 + mt * 16;
                a[mt][0] = Xs[(r0 + g) * CLD + k0 + tg];
                a[mt][1] = Xs[(r0 + 8 + g) * CLD + k0 + tg];
                a[mt][2] = Xs[(r0 + g) * CLD + k0 + tg + 4];
                a[mt][3] = Xs[(r0 + 8 + g) * CLD + k0 + tg + 4];
                if (CVTA) {
#pragma unroll
                    for (int q = 0; q < 4; q++)
                        a[mt][q] = f2tf32(__uint_as_float(a[mt][q]));
                }
            }
#pragma unroll
            for (int nt = 0; nt < 8; nt++) {
                int c0 = wn * 64 + nt * 8;
                uint32_t b0 = Ws[(c0 + g) * CLD + k0 + tg];
                uint32_t b1 = Ws[(c0 + g) * CLD + k0 + tg + 4];
                mma_tf32(acc[0][nt], a[0], b0, b1);
                mma_tf32(acc[1][nt], a[1], b0, b1);
            }
        }
        __syncthreads();
        if (c + 2 < 4) {
            stage_x(c + 2);
            asm volatile("cp.async.commit_group;" ::: "memory");
        }
    }

    // Epilogue: dinv scale, half2 pack into smem [128][ELD], coalesced STG.128.
    __syncthreads();   // all smem chunk reads complete; smem reusable
#pragma unroll
    for (int mt = 0; mt < 2; mt++) {
        int rl0 = wm * 32 + mt * 16 + g;
        int rl1 = rl0 + 8;
        int gr0 = row0 + rl0, gr1 = row0 + rl1;
        float dv0 = (gr0 < n) ? rsqrtf(1.0f + (float)cnt[gr0]) : 0.f;
        float dv1 = (gr1 < n) ? rsqrtf(1.0f + (float)cnt[gr1]) : 0.f;
#pragma unroll
        for (int nt = 0; nt < 8; nt++) {
            int cu = wn * 32 + nt * 4 + tg;   // u32 (half2) column index
            __half2 h0 = __floats2half2_rn(acc[mt][nt][0] * dv0, acc[mt][nt][1] * dv0);
            __half2 h1 = __floats2half2_rn(acc[mt][nt][2] * dv1, acc[mt][nt][3] * dv1);
            smem[rl0 * ELD + cu] = *(uint32_t*)&h0;
            smem[rl1 * ELD + cu] = *(uint32_t*)&h1;
        }
    }
    __syncthreads();

    uint4* H16 = (uint4*)H;   // 16 uint4 per row (256 B)
#pragma unroll
    for (int k = 0; k < 8; k++) {
        int idx = tid + k * 256;
        int row = idx >> 4, q = idx & 15;
        int gr = row0 + row;
        if (gr < n) {
            uint4 v;
            v.x = smem[row * ELD + q * 4 + 0];
            v.y = smem[row * ELD + q * 4 + 1];
            v.z = smem[row * ELD + q * 4 + 2];
            v.w = smem[row * ELD + q * 4 + 3];
            H16[(size_t)gr * 16 + q] = v;
        }
    }
}

// ---------------------------------------------------------------------------
// Pull aggregation (layers 1-2): one warp per node, fp16 gather, 8-deep MLP.
// OUT[v] = rna_tf32(relu(bias + dinv[v] * (H'[v] + sum_{s in in(v)} H'[s])))
// ---------------------------------------------------------------------------
__global__ void k_pull(const int* __restrict__ bucket, const int* __restrict__ cnt,
                       const __half* __restrict__ H,
                       const float* __restrict__ bias, float* __restrict__ OUT, int n) {
    int warp = (blockIdx.x * blockDim.x + threadIdx.x) >> 5;
    int lane = threadIdx.x & 31;
    if (warp >= n) return;
    const int v = warp;
    int rawdeg = cnt[v];
    int deg = rawdeg > CAP ? CAP : rawdeg;
    const int* bk = bucket + (size_t)v * CAP;
    const uint2* H2 = (const uint2*)H;

    float4 acc[4];
    {   // self-loop term
        uint2 raw = H2[(size_t)v * 32 + lane];
        float2 lo = __half22float2(*(__half2*)&raw.x);
        float2 hi = __half22float2(*(__half2*)&raw.y);
        acc[0] = make_float4(lo.x, lo.y, hi.x, hi.y);
        acc[1] = make_float4(0.f, 0.f, 0.f, 0.f);
        acc[2] = make_float4(0.f, 0.f, 0.f, 0.f);
        acc[3] = make_float4(0.f, 0.f, 0.f, 0.f);
    }

    for (int base = 0; base < deg; base += 32) {
        int m = deg - base; if (m > 32) m = 32;
        int myS = (lane < m) ? bk[base + lane] : 0;
        gather_block(H2, myS, m, lane, acc);
    }

    float dv = rsqrtf(1.0f + (float)rawdeg);
    const float4 bb = ((const float4*)bias)[lane];
    float sx = (acc[0].x + acc[1].x) + (acc[2].x + acc[3].x);
    float sy = (acc[0].y + acc[1].y) + (acc[2].y + acc[3].y);
    float sz = (acc[0].z + acc[1].z) + (acc[2].z + acc[3].z);
    float sw = (acc[0].w + acc[1].w) + (acc[2].w + acc[3].w);
    float4 o;
    o.x = __uint_as_float(f2tf32(fmaxf(fmaf(sx, dv, bb.x), 0.f)));
    o.y = __uint_as_float(f2tf32(fmaxf(fmaf(sy, dv, bb.y), 0.f)));
    o.z = __uint_as_float(f2tf32(fmaxf(fmaf(sz, dv, bb.z), 0.f)));
    o.w = __uint_as_float(f2tf32(fmaxf(fmaf(sw, dv, bb.w), 0.f)));
    ((float4*)OUT)[(size_t)v * 32 + lane] = o;
}

// ---------------------------------------------------------------------------
// FUSED final pull + regressor on the 8192 target nodes (fp16, 8-deep MLP).
// ---------------------------------------------------------------------------
__global__ void k_pull_regress(
    const int* __restrict__ bucket, const int* __restrict__ cnt,
    const __half* __restrict__ H, const float* __restrict__ bias,
    const int* __restrict__ tgt, const float* __restrict__ Wr,
    const float* __restrict__ br, float* __restrict__ out, int ntgt) {
    __shared__ float Wrs[DIM * OUTD];
    __shared__ float brs[OUTD];
    int tid = threadIdx.x;
    for (int i = tid; i < DIM * OUTD; i += blockDim.x) Wrs[i] = Wr[i];
    if (tid < OUTD) brs[tid] = br[tid];
    __syncthreads();

    int warp = (blockIdx.x * blockDim.x + tid) >> 5;
    int lane = tid & 31;
    if (warp >= ntgt) return;
    const int v = tgt[warp];
    int rawdeg = cnt[v];
    int deg = rawdeg > CAP ? CAP : rawdeg;
    const int* bk = bucket + (size_t)v * CAP;
    const uint2* H2 = (const uint2*)H;

    float4 acc[4];
    {
        uint2 raw = H2[(size_t)v * 32 + lane];
        float2 lo = __half22float2(*(__half2*)&raw.x);
        float2 hi = __half22float2(*(__half2*)&raw.y);
        acc[0] = make_float4(lo.x, lo.y, hi.x, hi.y);
        acc[1] = make_float4(0.f, 0.f, 0.f, 0.f);
        acc[2] = make_float4(0.f, 0.f, 0.f, 0.f);
        acc[3] = make_float4(0.f, 0.f, 0.f, 0.f);
    }

    for (int base = 0; base < deg; base += 32) {
        int m = deg - base; if (m > 32) m = 32;
        int myS = (lane < m) ? bk[base + lane] : 0;
        gather_block(H2, myS, m, lane, acc);
    }

    float dv = rsqrtf(1.0f + (float)rawdeg);
    const float4 bb = ((const float4*)bias)[lane];
    float4 s;
    s.x = fmaxf(fmaf((acc[0].x + acc[1].x) + (acc[2].x + acc[3].x), dv, bb.x), 0.f);
    s.y = fmaxf(fmaf((acc[0].y + acc[1].y) + (acc[2].y + acc[3].y), dv, bb.y), 0.f);
    s.z = fmaxf(fmaf((acc[0].z + acc[1].z) + (acc[2].z + acc[3].z), dv, bb.z), 0.f);
    s.w = fmaxf(fmaf((acc[0].w + acc[1].w) + (acc[2].w + acc[3].w), dv, bb.w), 0.f);

    int k0 = lane * 4;
#pragma unroll
    for (int o = 0; o < OUTD; o++) {
        float p = s.x * Wrs[(k0 + 0) * OUTD + o]
                + s.y * Wrs[(k0 + 1) * OUTD + o]
                + s.z * Wrs[(k0 + 2) * OUTD + o]
                + s.w * Wrs[(k0 + 3) * OUTD + o];
#pragma unroll
        for (int off = 16; off > 0; off >>= 1)
            p += __shfl_xor_sync(0xffffffff, p, off);
        if (lane == 0) out[warp * OUTD + o] = p + brs[o];
    }
}

// ---------------------------------------------------------------------------
// Launch
// ---------------------------------------------------------------------------
extern "C" void kernel_launch(void* const* d_in, const int* in_sizes, int n_in,
                              void* d_out, int out_size) {
    const float* x    = (const float*)d_in[0];
    const int*   ei   = (const int*)d_in[1];
    const int*   tgt  = (const int*)d_in[2];
    const float* W1   = (const float*)d_in[3];
    const float* b1   = (const float*)d_in[4];
    const float* W2   = (const float*)d_in[5];
    const float* b2   = (const float*)d_in[6];
    const float* W3   = (const float*)d_in[7];
    const float* b3   = (const float*)d_in[8];
    const float* Wr   = (const float*)d_in[9];
    const float* br   = (const float*)d_in[10];
    float* out = (float*)d_out;

    const int n    = in_sizes[0] / DIM;
    const int E    = in_sizes[1] / 2;
    const int ntgt = in_sizes[2];
    const int* src = ei;
    const int* dst = ei + E;

    __half* H;
    float *A, *B, *Wt;
    int *cnt, *bucket;
    cudaGetSymbolAddress((void**)&H,      g_H);
    cudaGetSymbolAddress((void**)&A,      g_A);
    cudaGetSymbolAddress((void**)&B,      g_B);
    cudaGetSymbolAddress((void**)&Wt,     g_Wt);
    cudaGetSymbolAddress((void**)&cnt,    g_cnt);
    cudaGetSymbolAddress((void**)&bucket, g_bucket);

    cudaFuncSetAttribute(k_gemm_tc<true>, cudaFuncAttributeMaxDynamicSharedMemorySize,
                         GEMM_SMEM_BYTES);
    cudaFuncSetAttribute(k_gemm_tc<false>, cudaFuncAttributeMaxDynamicSharedMemorySize,
                         GEMM_SMEM_BYTES);

    const int TPB = 256;
    const int nBlk    = (n + TPB - 1) / TPB;
    const int eBlk    = (E + TPB - 1) / TPB;
    const int gemmBlk = (n + 127) / 128;
    const int pullBlk = ((n * 32) + TPB - 1) / TPB;
    const int prBlk   = ((ntgt * 32) + TPB - 1) / TPB;

    // 1: transpose+round weights, zero counts (fused); 2: buckets
    k_pre<<<48 + nBlk, TPB>>>(W1, W2, W3, Wt, cnt, n);
    k_fill<<<eBlk, TPB>>>(src, dst, cnt, bucket, E);

    // Conv 1: x -> A
    k_gemm_tc<true><<<gemmBlk, 256, GEMM_SMEM_BYTES>>>(x, Wt, cnt, H, n);
    k_pull<<<pullBlk, TPB>>>(bucket, cnt, H, b1, A, n);

    // Conv 2: A -> B
    k_gemm_tc<false><<<gemmBlk, 256, GEMM_SMEM_BYTES>>>(A, Wt + DIM * DIM, cnt, H, n);
    k_pull<<<pullBlk, TPB>>>(bucket, cnt, H, b2, B, n);

    // Conv 3 GEMM: B -> H, then fused target-only pull + regressor
    k_gemm_tc<false><<<gemmBlk, 256, GEMM_SMEM_BYTES>>>(B, Wt + 2 * DIM * DIM, cnt, H, n);
    k_pull_regress<<<prBlk, TPB>>>(bucket, cnt, H, b3, tgt, Wr, br, out, ntgt);
}